// round 14
// baseline (speedup 1.0000x reference)
#include <cuda_runtime.h>
#include <cuda_fp16.h>
#include <cstdint>

#define NP 100000
#define NA 100000
#define NF 50000
#define FIN 128
#define HID 64
#define OUTF 349

#define E_WR 1000000
#define E_RW 1000000
#define E_CI 2000000
#define E_HT 1000000
#define E_RH 1000000

#define CNT_TOT (NP + NA + NP + NF + NP)   // 450000

// ---------------- scratch ----------------
static __device__ __align__(256) __half g_hs_wr[NA * HID];
static __device__ __align__(256) __half g_hs_rw[NP * HID];
static __device__ __align__(256) __half g_hs_ci[NP * HID];
static __device__ __align__(256) __half g_hs_ht[NP * HID];
static __device__ __align__(256) __half g_hs_rh[NF * HID];
static __device__ __align__(256) __half g_selfP[NP * HID];
static __device__ __align__(256) __half g_selfA[NA * HID];
static __device__ __align__(256) __half g_selfF[NF * HID];
static __device__ __align__(256) __half g_p1h[NP * HID];
static __device__ __align__(256) __half g_a1h[NA * HID];
static __device__ __align__(256) __half g_f1h[NF * HID];
static __device__ __align__(256) __half g_m2_wr[NP * HID];
static __device__ __align__(256) __half g_m2_ci[NP * HID];
static __device__ __align__(256) __half g_m2_rh[NP * HID];
// CSR machinery
static __device__ int g_cnt[CNT_TOT];
static __device__ int g_fl[CNT_TOT];
static __device__ int g_rp_wr[NP + 1], g_rp_rw[NA + 1], g_rp_ci[NP + 1], g_rp_ht[NF + 1], g_rp_rh[NP + 1];
static __device__ int g_csr_wr[E_WR], g_csr_rw[E_RW], g_csr_ci[E_CI], g_csr_ht[E_HT], g_csr_rh[E_RH];
static __device__ int g_bsumA[5][128];
// summed weights / biases
static __device__ __align__(256) float g_wsumP[FIN * HID];
static __device__ __align__(256) float g_w2sum[HID * OUTF];
static __device__ __align__(256) float g_bsum1[HID];
static __device__ __align__(256) float g_bsum2[OUTF];

__constant__ int c_n[5] = {NP, NA, NP, NF, NP};
__constant__ int c_off[5] = {0, NP, NP + NA, NP + NA + NP, NP + NA + NP + NF};

__device__ __forceinline__ int* rp_of(int ty) {
    switch (ty) {
        case 0: return g_rp_wr;
        case 1: return g_rp_rw;
        case 2: return g_rp_ci;
        case 3: return g_rp_ht;
        default: return g_rp_rh;
    }
}
__device__ __forceinline__ int* csr_of(int ty) {
    switch (ty) {
        case 0: return g_csr_wr;
        case 1: return g_csr_rw;
        case 2: return g_csr_ci;
        case 3: return g_csr_ht;
        default: return g_csr_rh;
    }
}

// ---------------- fp16 MMA helpers ----------------
__device__ __forceinline__ uint32_t packh2(float a, float b) {
    __half2 h = __floats2half2_rn(a, b);
    return *reinterpret_cast<uint32_t*>(&h);
}

__device__ __forceinline__ void mma_f16(float c[4], uint32_t a0, uint32_t a1,
                                        uint32_t a2, uint32_t a3,
                                        uint32_t b0, uint32_t b1) {
    asm volatile("mma.sync.aligned.m16n8k16.row.col.f32.f16.f16.f32 "
                 "{%0,%1,%2,%3}, {%4,%5,%6,%7}, {%8,%9}, {%0,%1,%2,%3};"
                 : "+f"(c[0]), "+f"(c[1]), "+f"(c[2]), "+f"(c[3])
                 : "r"(a0), "r"(a1), "r"(a2), "r"(a3), "r"(b0), "r"(b1));
}

// ---------------- weight/bias prep ----------------
__global__ void prep_weights(const float* __restrict__ wr1a, const float* __restrict__ wr1b,
                             const float* __restrict__ wr1c,
                             const float* __restrict__ wr2a, const float* __restrict__ wr2b,
                             const float* __restrict__ wr2c,
                             const float* __restrict__ b1a, const float* __restrict__ b1b,
                             const float* __restrict__ b1c,
                             const float* __restrict__ b2a, const float* __restrict__ b2b,
                             const float* __restrict__ b2c) {
    int i = blockIdx.x * blockDim.x + threadIdx.x;
    if (i < FIN * HID) g_wsumP[i] = wr1a[i] + wr1b[i] + wr1c[i];
    if (i < HID * OUTF) g_w2sum[i] = wr2a[i] + wr2b[i] + wr2c[i];
    if (i < HID) g_bsum1[i] = b1a[i] + b1b[i] + b1c[i];
    if (i < OUTF) g_bsum2[i] = b2a[i] + b2b[i] + b2c[i];
}

// ---------------- CSR build ----------------
struct EJobs {
    const int* ei[5];
    int E[5];
    int bs[6];
};

__global__ void k_count_all(EJobs ep) {
    int b = blockIdx.x;
    int ty = 0;
    while (b >= ep.bs[ty + 1]) ++ty;
    int e = (b - ep.bs[ty]) * 256 + threadIdx.x;
    if (e >= ep.E[ty]) return;
    int d = __ldg(ep.ei[ty] + ep.E[ty] + e);
    atomicAdd(g_cnt + c_off[ty] + d, 1);
}

__global__ void k_blocksum_all() {
    __shared__ int s[256];
    int ty = blockIdx.y;
    int n = c_n[ty];
    int base = blockIdx.x * 1024;
    if (base >= n) { if (threadIdx.x == 0) g_bsumA[ty][blockIdx.x] = 0; return; }
    const int* c = g_cnt + c_off[ty];
    int t = threadIdx.x;
    int v = 0;
#pragma unroll
    for (int j = 0; j < 4; ++j) {
        int i = base + t * 4 + j;
        if (i < n) v += c[i];
    }
    s[t] = v;
    __syncthreads();
    for (int o = 128; o > 0; o >>= 1) {
        if (t < o) s[t] += s[t + o];
        __syncthreads();
    }
    if (t == 0) g_bsumA[ty][blockIdx.x] = s[0];
}

__global__ void k_scan_bsums_all() {
    __shared__ int s[256];
    int ty = blockIdx.x;
    int n = c_n[ty];
    int nb = (n + 1023) / 1024;
    int t = threadIdx.x;
    int v = (t < nb) ? g_bsumA[ty][t] : 0;
    s[t] = v;
    __syncthreads();
    for (int o = 1; o < 256; o <<= 1) {
        int x = (t >= o) ? s[t - o] : 0;
        __syncthreads();
        s[t] += x;
        __syncthreads();
    }
    if (t < nb) g_bsumA[ty][t] = s[t] - v;
    if (t == 0) rp_of(ty)[n] = s[255];
}

__global__ void k_scan_write_all() {
    __shared__ int s[256];
    int ty = blockIdx.y;
    int n = c_n[ty];
    int base = blockIdx.x * 1024;
    if (base >= n) return;
    const int* c = g_cnt + c_off[ty];
    int* rowptr = rp_of(ty);
    int* fill = g_fl + c_off[ty];
    int t = threadIdx.x;
    int loc[4];
    int v = 0;
#pragma unroll
    for (int j = 0; j < 4; ++j) {
        int i = base + t * 4 + j;
        loc[j] = v;
        v += (i < n) ? c[i] : 0;
    }
    s[t] = v;
    __syncthreads();
    for (int o = 1; o < 256; o <<= 1) {
        int x = (t >= o) ? s[t - o] : 0;
        __syncthreads();
        s[t] += x;
        __syncthreads();
    }
    int ex = s[t] - v;
    int off = g_bsumA[ty][blockIdx.x] + ex;
#pragma unroll
    for (int j = 0; j < 4; ++j) {
        int i = base + t * 4 + j;
        if (i < n) {
            int r = off + loc[j];
            rowptr[i] = r;
            fill[i] = r;
        }
    }
}

__global__ void k_fill_all(EJobs ep) {
    int b = blockIdx.x;
    int ty = 0;
    while (b >= ep.bs[ty + 1]) ++ty;
    int e = (b - ep.bs[ty]) * 256 + threadIdx.x;
    if (e >= ep.E[ty]) return;
    int s = __ldg(ep.ei[ty] + e);
    int d = __ldg(ep.ei[ty] + ep.E[ty] + e);
    int pos = atomicAdd(g_fl + c_off[ty] + d, 1);
    csr_of(ty)[pos] = s;
}

// ---------------- pull primitives (735-proven versions) ----------------
__device__ __forceinline__ void acc_h8_s(float acc[8], uint4 v, float s) {
    float2 f0 = __half22float2(*reinterpret_cast<const __half2*>(&v.x));
    float2 f1 = __half22float2(*reinterpret_cast<const __half2*>(&v.y));
    float2 f2 = __half22float2(*reinterpret_cast<const __half2*>(&v.z));
    float2 f3 = __half22float2(*reinterpret_cast<const __half2*>(&v.w));
    acc[0] += f0.x * s; acc[1] += f0.y * s;
    acc[2] += f1.x * s; acc[3] += f1.y * s;
    acc[4] += f2.x * s; acc[5] += f2.y * s;
    acc[6] += f3.x * s; acc[7] += f3.y * s;
}

__device__ __forceinline__ void acc_h8(float acc[8], uint4 v) {
    float2 f0 = __half22float2(*reinterpret_cast<const __half2*>(&v.x));
    float2 f1 = __half22float2(*reinterpret_cast<const __half2*>(&v.y));
    float2 f2 = __half22float2(*reinterpret_cast<const __half2*>(&v.z));
    float2 f3 = __half22float2(*reinterpret_cast<const __half2*>(&v.w));
    acc[0] += f0.x; acc[1] += f0.y;
    acc[2] += f1.x; acc[3] += f1.y;
    acc[4] += f2.x; acc[5] += f2.y;
    acc[6] += f3.x; acc[7] += f3.y;
}

__device__ __forceinline__ void shfl_reduce8(float acc[8]) {
#pragma unroll
    for (int i = 0; i < 8; ++i) {
        acc[i] += __shfl_xor_sync(0xffffffffu, acc[i], 8);
        acc[i] += __shfl_xor_sync(0xffffffffu, acc[i], 16);
    }
}

__device__ __forceinline__ uint4 pack_h8v(const float v[8]) {
    uint4 o;
    *reinterpret_cast<__half2*>(&o.x) = __floats2half2_rn(v[0], v[1]);
    *reinterpret_cast<__half2*>(&o.y) = __floats2half2_rn(v[2], v[3]);
    *reinterpret_cast<__half2*>(&o.z) = __floats2half2_rn(v[4], v[5]);
    *reinterpret_cast<__half2*>(&o.w) = __floats2half2_rn(v[6], v[7]);
    return o;
}

// branchless single-list pull: 4 clamp-indexed loads per iteration, scaled add.
__device__ __forceinline__ void pull1_scaled(const __half* __restrict__ feat,
                                             const int* __restrict__ csr,
                                             int beg, int end, int team, int c,
                                             float inv, float acc[8]) {
    int j = beg + team;
    while (j < end) {
        bool p1 = j + 4 < end, p2 = j + 8 < end, p3 = j + 12 < end;
        int i0 = j;
        int i1 = p1 ? j + 4 : i0;
        int i2 = p2 ? j + 8 : i0;
        int i3 = p3 ? j + 12 : i0;
        int s0 = __ldg(csr + i0);
        int s1 = __ldg(csr + i1);
        int s2 = __ldg(csr + i2);
        int s3 = __ldg(csr + i3);
        uint4 v0 = *(const uint4*)(feat + (size_t)s0 * HID + c * 8);
        uint4 v1 = *(const uint4*)(feat + (size_t)s1 * HID + c * 8);
        uint4 v2 = *(const uint4*)(feat + (size_t)s2 * HID + c * 8);
        uint4 v3 = *(const uint4*)(feat + (size_t)s3 * HID + c * 8);
        acc_h8_s(acc, v0, inv);
        acc_h8_s(acc, v1, p1 ? inv : 0.f);
        acc_h8_s(acc, v2, p2 ? inv : 0.f);
        acc_h8_s(acc, v3, p3 ? inv : 0.f);
        j += 16;
    }
}

// layer-1 paper: 3 edge lists fused in one loop (6 gathers/iter in flight),
// one scaled accumulator, one shfl tree.
__global__ void k_paper_warp() {
    int wg = (blockIdx.x * blockDim.x + threadIdx.x) >> 5;
    if (wg >= NP) return;
    int lane = threadIdx.x & 31;
    int team = lane >> 3, c = lane & 7;

    int bw = __ldg(g_rp_wr + wg), ew = __ldg(g_rp_wr + wg + 1);
    int bc = __ldg(g_rp_ci + wg), ec = __ldg(g_rp_ci + wg + 1);
    int br = __ldg(g_rp_rh + wg), er = __ldg(g_rp_rh + wg + 1);
    float invw = 1.f / fmaxf((float)(ew - bw), 1.f);
    float invc = 1.f / fmaxf((float)(ec - bc), 1.f);
    float invr = 1.f / fmaxf((float)(er - br), 1.f);

    float acc[8] = {};
    int jw = bw + team, jc = bc + team, jr = br + team;
    while (jw < ew || jc < ec || jr < er) {
        bool pw0 = jw < ew, pw1 = jw + 4 < ew;
        bool pc0 = jc < ec, pc1 = jc + 4 < ec;
        bool pr0 = jr < er, pr1 = jr + 4 < er;
        int iw0 = pw0 ? jw : 0, iw1 = pw1 ? jw + 4 : iw0;
        int ic0 = pc0 ? jc : 0, ic1 = pc1 ? jc + 4 : ic0;
        int ir0 = pr0 ? jr : 0, ir1 = pr1 ? jr + 4 : ir0;
        int sw0 = __ldg(g_csr_wr + iw0), sw1 = __ldg(g_csr_wr + iw1);
        int sc0 = __ldg(g_csr_ci + ic0), sc1 = __ldg(g_csr_ci + ic1);
        int sr0 = __ldg(g_csr_rh + ir0), sr1 = __ldg(g_csr_rh + ir1);
        uint4 vw0 = *(const uint4*)(g_hs_wr + (size_t)sw0 * HID + c * 8);
        uint4 vw1 = *(const uint4*)(g_hs_wr + (size_t)sw1 * HID + c * 8);
        uint4 vc0 = *(const uint4*)(g_hs_ci + (size_t)sc0 * HID + c * 8);
        uint4 vc1 = *(const uint4*)(g_hs_ci + (size_t)sc1 * HID + c * 8);
        uint4 vr0 = *(const uint4*)(g_hs_rh + (size_t)sr0 * HID + c * 8);
        uint4 vr1 = *(const uint4*)(g_hs_rh + (size_t)sr1 * HID + c * 8);
        acc_h8_s(acc, vw0, pw0 ? invw : 0.f);
        acc_h8_s(acc, vw1, pw1 ? invw : 0.f);
        acc_h8_s(acc, vc0, pc0 ? invc : 0.f);
        acc_h8_s(acc, vc1, pc1 ? invc : 0.f);
        acc_h8_s(acc, vr0, pr0 ? invr : 0.f);
        acc_h8_s(acc, vr1, pr1 ? invr : 0.f);
        jw += 8; jc += 8; jr += 8;
    }
    shfl_reduce8(acc);
    if (team == 0) {
        uint4 sv = *(const uint4*)(g_selfP + (size_t)wg * HID + c * 8);
        acc_h8(acc, sv);
        float o[8];
#pragma unroll
        for (int i = 0; i < 8; ++i)
            o[i] = fmaxf(acc[i] + g_bsum1[c * 8 + i], 0.f);
        *(uint4*)(g_p1h + (size_t)wg * HID + c * 8) = pack_h8v(o);
    }
}

// layer-1 author/field: 1 pull + self + bias + relu -> fp16 out
__global__ void k_af_warp(const __half* __restrict__ feat, const int* __restrict__ rowptr,
                          const int* __restrict__ csr, const __half* __restrict__ selfX,
                          const float* __restrict__ bias, __half* __restrict__ out, int n) {
    int wg = (blockIdx.x * blockDim.x + threadIdx.x) >> 5;
    if (wg >= n) return;
    int lane = threadIdx.x & 31;
    int team = lane >> 3, c = lane & 7;
    int beg = __ldg(rowptr + wg), end = __ldg(rowptr + wg + 1);
    float inv = 1.f / fmaxf((float)(end - beg), 1.f);
    float acc[8] = {};
    pull1_scaled(feat, csr, beg, end, team, c, inv, acc);
    shfl_reduce8(acc);
    if (team == 0) {
        uint4 sv = *(const uint4*)(selfX + (size_t)wg * HID + c * 8);
        acc_h8(acc, sv);
        float o[8];
#pragma unroll
        for (int i = 0; i < 8; ++i)
            o[i] = fmaxf(acc[i] + bias[c * 8 + i], 0.f);
        *(uint4*)(out + (size_t)wg * HID + c * 8) = pack_h8v(o);
    }
}

// layer-2 single pull -> fp16 mean buffer
__global__ void k_l2_warp(const __half* __restrict__ feat, const int* __restrict__ rowptr,
                          const int* __restrict__ csr, __half* __restrict__ out, int n) {
    int wg = (blockIdx.x * blockDim.x + threadIdx.x) >> 5;
    if (wg >= n) return;
    int lane = threadIdx.x & 31;
    int team = lane >> 3, c = lane & 7;
    int beg = __ldg(rowptr + wg), end = __ldg(rowptr + wg + 1);
    float inv = 1.f / fmaxf((float)(end - beg), 1.f);
    float acc[8] = {};
    pull1_scaled(feat, csr, beg, end, team, c, inv, acc);
    shfl_reduce8(acc);
    if (team == 0)
        *(uint4*)(out + (size_t)wg * HID + c * 8) = pack_h8v(acc);
}

// ---------------- fp16 HMMA GEMM: C[M,64](fp16) = A[M,128] @ B[128,64], batched ----------------
struct GemmBatch {
    const float* B[4];
    __half* C[4];
};

__global__ void gemm_f16_f128(const float* __restrict__ A, GemmBatch p, int M) {
    __shared__ uint32_t As[128 * 20];
    __shared__ uint32_t Bs[64 * 20];
    const float* __restrict__ Bp = p.B[blockIdx.y];
    __half* __restrict__ Cp = p.C[blockIdx.y];
    const int t = threadIdx.x;
    const int wid = t >> 5, lane = t & 31;
    const int g = lane >> 2, tg = lane & 3;
    const int rowBase = blockIdx.x * 128;
    const int wrow = wid * 16;

    float c[8][4] = {};

    for (int kb = 0; kb < 4; ++kb) {
#pragma unroll
        for (int j = 0; j < 4; ++j) {
            int idx = t + j * 256;
            int r = idx >> 3, q = idx & 7;
            int gr = rowBase + r;
            if (gr >= M) gr = M - 1;
            float4 av = *(const float4*)(A + (size_t)gr * FIN + kb * 32 + q * 4);
            As[r * 20 + q * 2 + 0] = packh2(av.x, av.y);
            As[r * 20 + q * 2 + 1] = packh2(av.z, av.w);
        }
#pragma unroll
        for (int j = 0; j < 4; ++j) {
            int idx = t + j * 256;
            int n = idx & 63, kh = idx >> 6;
            float v0 = Bp[(size_t)(kb * 32 + 2 * kh) * HID + n];
            float v1 = Bp[(size_t)(kb * 32 + 2 * kh + 1) * HID + n];
            Bs[n * 20 + kh] = packh2(v0, v1);
        }
        __syncthreads();
#pragma unroll
        for (int ks = 0; ks < 2; ++ks) {
            int kh0 = ks * 8;
            uint32_t a0 = As[(wrow + g) * 20 + kh0 + tg];
            uint32_t a1 = As[(wrow + g + 8) * 20 + kh0 + tg];
            uint32_t a2 = As[(wrow + g) * 20 + kh0 + tg + 4];
            uint32_t a3 = As[(wrow + g + 8) * 20 + kh0 + tg + 4];
#pragma unroll
            for (int nt = 0; nt < 8; ++nt) {
                int n = nt * 8 + g;
                uint32_t b0 = Bs[n * 20 + kh0 + tg];
                uint32_t b1 = Bs[n * 20 + kh0 + tg + 4];
                mma_f16(c[nt], a0, a1, a2, a3, b0, b1);
            }
        }
        __syncthreads();
    }

    int r0 = rowBase + wrow + g, r1 = r0 + 8;
#pragma unroll
    for (int nt = 0; nt < 8; ++nt) {
        int col = nt * 8 + tg * 2;
        if (r0 < M)
            *reinterpret_cast<__half2*>(Cp + (size_t)r0 * HID + col) = __floats2half2_rn(c[nt][0], c[nt][1]);
        if (r1 < M)
            *reinterpret_cast<__half2*>(Cp + (size_t)r1 * HID + col) = __floats2half2_rn(c[nt][2], c[nt][3]);
    }
}

// ---------------- fp16 HMMA output GEMM (partial, NSRC sources) ----------------
// INIT=true: C = acc + bias; INIT=false: C += acc
template <int NSRC, bool INIT>
__global__ void gemm_out_part(const __half* __restrict__ A0, const __half* __restrict__ A1,
                              const __half* __restrict__ A2,
                              const float* __restrict__ B0, const float* __restrict__ B1,
                              const float* __restrict__ B2,
                              float* __restrict__ C, int M) {
    __shared__ uint32_t As[128 * 20];
    __shared__ uint32_t Bs[64 * 20];
    const int t = threadIdx.x;
    const int wid = t >> 5, lane = t & 31;
    const int g = lane >> 2, tg = lane & 3;
    const int rowBase = blockIdx.x * 128;
    const int colBase = blockIdx.y * 64;
    const int wrow = wid * 16;

    const __half* Aps[3] = {A0, A1, A2};
    const float* Bps[3] = {B0, B1, B2};

    float c[8][4] = {};

#pragma unroll
    for (int m = 0; m < NSRC; ++m) {
        const __half* __restrict__ Ap = Aps[m];
        const float* __restrict__ Bp = Bps[m];
        for (int kb = 0; kb < 2; ++kb) {
#pragma unroll
            for (int j = 0; j < 2; ++j) {
                int idx = t + j * 256;
                int r = idx >> 2, q = idx & 3;
                int gr = rowBase + r;
                if (gr >= M) gr = M - 1;
                uint4 hv = *(const uint4*)(Ap + (size_t)gr * HID + kb * 32 + q * 8);
                uint32_t* d = &As[r * 20 + q * 4];
                d[0] = hv.x; d[1] = hv.y; d[2] = hv.z; d[3] = hv.w;
            }
#pragma unroll
            for (int j = 0; j < 4; ++j) {
                int idx = t + j * 256;
                int n = idx & 63, kh = idx >> 6;
                int col = colBase + n;
                float v0 = 0.f, v1 = 0.f;
                if (col < OUTF) {
                    v0 = Bp[(size_t)(kb * 32 + 2 * kh) * OUTF + col];
                    v1 = Bp[(size_t)(kb * 32 + 2 * kh + 1) * OUTF + col];
                }
                Bs[n * 20 + kh] = packh2(v0, v1);
            }
            __syncthreads();
#pragma unroll
            for (int ks = 0; ks < 2; ++ks) {
                int kh0 = ks * 8;
                uint32_t a0 = As[(wrow + g) * 20 + kh0 + tg];
                uint32_t a1 = As[(wrow + g + 8) * 20 + kh0 + tg];
                uint32_t a2 = As[(wrow + g) * 20 + kh0 + tg + 4];
                uint32_t a3 = As[(wrow + g + 8) * 20 + kh0 + tg + 4];
#pragma unroll
                for (int nt = 0; nt < 8; ++nt) {
                    int n = nt * 8 + g;
                    uint32_t b0 = Bs[n * 20 + kh0 + tg];
                    uint32_t b1 = Bs[n * 20 + kh0 + tg + 4];
                    mma_f16(c[nt], a0, a1, a2, a3, b0, b1);
                }
            }
            __syncthreads();
        }
    }

    int r0 = rowBase + wrow + g, r1 = r0 + 8;
#pragma unroll
    for (int nt = 0; nt < 8; ++nt) {
#pragma unroll
        for (int q = 0; q < 2; ++q) {
            int col = colBase + nt * 8 + tg * 2 + q;
            if (col >= OUTF) continue;
            float v0 = c[nt][q], v1 = c[nt][2 + q];
            if (INIT) {
                float b = g_bsum2[col];
                if (r0 < M) C[(size_t)r0 * OUTF + col] = v0 + b;
                if (r1 < M) C[(size_t)r1 * OUTF + col] = v1 + b;
            } else {
                if (r0 < M) C[(size_t)r0 * OUTF + col] += v0;
                if (r1 < M) C[(size_t)r1 * OUTF + col] += v1;
            }
        }
    }
}

// ---------------- host launcher ----------------
static inline void* sym(const void* s) {
    void* p = nullptr;
    cudaGetSymbolAddress(&p, s);
    return p;
}

extern "C" void kernel_launch(void* const* d_in, const int* in_sizes, int n_in,
                              void* d_out, int out_size) {
    static cudaStream_t s1 = nullptr, s2 = nullptr;
    static cudaEvent_t ev0 = nullptr, ev1 = nullptr, ev2 = nullptr, ev3 = nullptr,
                       ev4 = nullptr, evP = nullptr, evA = nullptr;
    if (s1 == nullptr) {
        cudaStreamCreateWithFlags(&s1, cudaStreamNonBlocking);
        cudaStreamCreateWithFlags(&s2, cudaStreamNonBlocking);
        cudaEventCreateWithFlags(&ev0, cudaEventDisableTiming);
        cudaEventCreateWithFlags(&ev1, cudaEventDisableTiming);
        cudaEventCreateWithFlags(&ev2, cudaEventDisableTiming);
        cudaEventCreateWithFlags(&ev3, cudaEventDisableTiming);
        cudaEventCreateWithFlags(&ev4, cudaEventDisableTiming);
        cudaEventCreateWithFlags(&evP, cudaEventDisableTiming);
        cudaEventCreateWithFlags(&evA, cudaEventDisableTiming);
    }

    const float* x_paper  = (const float*)d_in[0];
    const float* x_author = (const float*)d_in[1];
    const float* x_field  = (const float*)d_in[2];
    const int* ei_wr = (const int*)d_in[3];
    const int* ei_rw = (const int*)d_in[4];
    const int* ei_ci = (const int*)d_in[5];
    const int* ei_ht = (const int*)d_in[6];
    const int* ei_rh = (const int*)d_in[7];
    const int nE_wr = in_sizes[3] / 2;
    const int nE_rw = in_sizes[4] / 2;
    const int nE_ci = in_sizes[5] / 2;
    const int nE_ht = in_sizes[6] / 2;
    const int nE_rh = in_sizes[7] / 2;

    const float* wl1_wr = (const float*)d_in[8];
    const float* wr1_wr = (const float*)d_in[9];
    const float* b1_wr  = (const float*)d_in[10];
    const float* wl1_rw = (const float*)d_in[11];
    const float* wr1_rw = (const float*)d_in[12];
    const float* b1_rw  = (const float*)d_in[13];
    const float* wl1_ci = (const float*)d_in[14];
    const float* wr1_ci = (const float*)d_in[15];
    const float* b1_ci  = (const float*)d_in[16];
    const float* wl1_ht = (const float*)d_in[17];
    const float* wr1_ht = (const float*)d_in[18];
    const float* b1_ht  = (const float*)d_in[19];
    const float* wl1_rh = (const float*)d_in[20];
    const float* wr1_rh = (const float*)d_in[21];
    const float* b1_rh  = (const float*)d_in[22];
    const float* wl2_wr = (const float*)d_in[23];
    const float* wr2_wr = (const float*)d_in[24];
    const float* b2_wr  = (const float*)d_in[25];
    const float* wl2_ci = (const float*)d_in[26];
    const float* wr2_ci = (const float*)d_in[27];
    const float* b2_ci  = (const float*)d_in[28];
    const float* wl2_rh = (const float*)d_in[29];
    const float* wr2_rh = (const float*)d_in[30];
    const float* b2_rh  = (const float*)d_in[31];

    float* out = (float*)d_out;

    __half* hs_wr = (__half*)sym(g_hs_wr);
    __half* hs_rw = (__half*)sym(g_hs_rw);
    __half* hs_ci = (__half*)sym(g_hs_ci);
    __half* hs_ht = (__half*)sym(g_hs_ht);
    __half* hs_rh = (__half*)sym(g_hs_rh);
    __half* selfP = (__half*)sym(g_selfP);
    __half* selfA = (__half*)sym(g_selfA);
    __half* selfF = (__half*)sym(g_selfF);
    __half* a1h = (__half*)sym(g_a1h);
    __half* f1h = (__half*)sym(g_f1h);
    __half* p1h = (__half*)sym(g_p1h);
    __half* m2_wr = (__half*)sym(g_m2_wr);
    __half* m2_ci = (__half*)sym(g_m2_ci);
    __half* m2_rh = (__half*)sym(g_m2_rh);
    int* cnt = (int*)sym(g_cnt);
    int* rp_wr = (int*)sym(g_rp_wr);
    int* rp_rw = (int*)sym(g_rp_rw);
    int* rp_ci = (int*)sym(g_rp_ci);
    int* rp_ht = (int*)sym(g_rp_ht);
    int* rp_rh = (int*)sym(g_rp_rh);
    int* csr_wr = (int*)sym(g_csr_wr);
    int* csr_rw = (int*)sym(g_csr_rw);
    int* csr_ci = (int*)sym(g_csr_ci);
    int* csr_ht = (int*)sym(g_csr_ht);
    int* csr_rh = (int*)sym(g_csr_rh);
    float* wsumP = (float*)sym(g_wsumP);
    float* w2sum = (float*)sym(g_w2sum);

    // ---- fork: s1 does weight prep + layer-1 GEMMs ----
    cudaEventRecord(ev0, 0);
    cudaStreamWaitEvent(s1, ev0, 0);

    prep_weights<<<(HID * OUTF + 255) / 256, 256, 0, s1>>>(
        wr1_wr, wr1_ci, wr1_rh, wr2_wr, wr2_ci, wr2_rh,
        b1_wr, b1_ci, b1_rh, b2_wr, b2_ci, b2_rh);

    const int gP = (NP + 127) / 128, gA = (NA + 127) / 128, gF = (NF + 127) / 128;
    {
        GemmBatch bp;
        bp.B[0] = wl1_rw; bp.C[0] = hs_rw;
        bp.B[1] = wl1_ci; bp.C[1] = hs_ci;
        bp.B[2] = wl1_ht; bp.C[2] = hs_ht;
        bp.B[3] = wsumP;  bp.C[3] = selfP;
        gemm_f16_f128<<<dim3(gP, 4), 256, 0, s1>>>(x_paper, bp, NP);
        GemmBatch ba;
        ba.B[0] = wl1_wr; ba.C[0] = hs_wr;
        ba.B[1] = wr1_rw; ba.C[1] = selfA;
        ba.B[2] = wl1_wr; ba.C[2] = hs_wr;
        ba.B[3] = wl1_wr; ba.C[3] = hs_wr;
        gemm_f16_f128<<<dim3(gA, 2), 256, 0, s1>>>(x_author, ba, NA);
        GemmBatch bf;
        bf.B[0] = wl1_rh; bf.C[0] = hs_rh;
        bf.B[1] = wr1_ht; bf.C[1] = selfF;
        bf.B[2] = wl1_rh; bf.C[2] = hs_rh;
        bf.B[3] = wl1_rh; bf.C[3] = hs_rh;
        gemm_f16_f128<<<dim3(gF, 2), 256, 0, s1>>>(x_field, bf, NF);
    }
    cudaEventRecord(ev1, s1);

    // ---- stream 0: CSR build ----
    cudaMemsetAsync(cnt, 0, sizeof(int) * CNT_TOT, 0);

    EJobs ep;
    ep.ei[0] = ei_wr; ep.E[0] = nE_wr;
    ep.ei[1] = ei_rw; ep.E[1] = nE_rw;
    ep.ei[2] = ei_ci; ep.E[2] = nE_ci;
    ep.ei[3] = ei_ht; ep.E[3] = nE_ht;
    ep.ei[4] = ei_rh; ep.E[4] = nE_rh;
    ep.bs[0] = 0;
    for (int i = 0; i < 5; ++i) ep.bs[i + 1] = ep.bs[i] + (ep.E[i] + 255) / 256;

    k_count_all<<<ep.bs[5], 256>>>(ep);
    k_blocksum_all<<<dim3((NP + 1023) / 1024, 5), 256>>>();
    k_scan_bsums_all<<<5, 256>>>();
    k_scan_write_all<<<dim3((NP + 1023) / 1024, 5), 256>>>();
    k_fill_all<<<ep.bs[5], 256>>>(ep);
    cudaEventRecord(ev2, 0);

    auto wg = [](int n) { return (n * 32 + 255) / 256; };

    // ---- stream 0 chain: paper layer-1 -> layer-2 ci pull ----
    cudaStreamWaitEvent(0, ev1, 0);      // needs hs_* from s1
    k_paper_warp<<<wg(NP), 256>>>();
    cudaEventRecord(evP, 0);             // p1h ready
    k_l2_warp<<<wg(NP), 256>>>(p1h, rp_ci, csr_ci, m2_ci, NP);

    // ---- s1 chain: author layer-1 -> layer-2 wr pull ----
    cudaStreamWaitEvent(s1, ev2, 0);     // needs CSR from stream 0
    k_af_warp<<<wg(NA), 256, 0, s1>>>(hs_rw, rp_rw, csr_rw, selfA, b1_rw, a1h, NA);
    k_l2_warp<<<wg(NP), 256, 0, s1>>>(a1h, rp_wr, csr_wr, m2_wr, NP);
    cudaEventRecord(ev3, s1);

    // ---- s2 chain: field layer-1 -> layer-2 rh pull ----
    cudaStreamWaitEvent(s2, ev1, 0);
    cudaStreamWaitEvent(s2, ev2, 0);
    k_af_warp<<<wg(NF), 256, 0, s2>>>(hs_ht, rp_ht, csr_ht, selfF, b1_ht, f1h, NF);
    k_l2_warp<<<wg(NP), 256, 0, s2>>>(f1h, rp_rh, csr_rh, m2_rh, NP);
    cudaEventRecord(ev4, s2);

    // ---- gemm_out launch A (s1): 3 ready chunks, overlaps l2_ci pull ----
    dim3 g2(gP, (OUTF + 63) / 64);
    cudaStreamWaitEvent(s1, ev4, 0);     // rh pull done (s1 already has wr pull done in-stream)
    cudaStreamWaitEvent(s1, evP, 0);     // p1h ready
    gemm_out_part<3, true><<<g2, 256, 0, s1>>>(m2_wr, m2_rh, p1h,
                                               wl2_wr, wl2_rh, w2sum,
                                               out, NP);
    cudaEventRecord(evA, s1);

    // ---- gemm_out launch B (stream 0, after l2_ci + A): accumulate ci chunk ----
    cudaStreamWaitEvent(0, evA, 0);
    gemm_out_part<1, false><<<g2, 256>>>(m2_ci, nullptr, nullptr,
                                         wl2_ci, nullptr, nullptr,
                                         out, NP);
}

// round 15
// speedup vs baseline: 1.2410x; 1.2410x over previous
#include <cuda_runtime.h>
#include <cuda_fp16.h>
#include <cstdint>

#define NP 100000
#define NA 100000
#define NF 50000
#define FIN 128
#define HID 64
#define OUTF 349

#define E_WR 1000000
#define E_RW 1000000
#define E_CI 2000000
#define E_HT 1000000
#define E_RH 1000000

#define CNT_TOT (NP + NA + NP + NF + NP)   // 450000

// ---------------- scratch ----------------
static __device__ __align__(256) __half g_hs_wr[NA * HID];
static __device__ __align__(256) __half g_hs_rw[NP * HID];
static __device__ __align__(256) __half g_hs_ci[NP * HID];
static __device__ __align__(256) __half g_hs_ht[NP * HID];
static __device__ __align__(256) __half g_hs_rh[NF * HID];
static __device__ __align__(256) __half g_selfP[NP * HID];
static __device__ __align__(256) __half g_selfA[NA * HID];
static __device__ __align__(256) __half g_selfF[NF * HID];
static __device__ __align__(256) __half g_p1h[NP * HID];
static __device__ __align__(256) __half g_a1h[NA * HID];
static __device__ __align__(256) __half g_f1h[NF * HID];
static __device__ __align__(256) __half g_m2_wr[NP * HID];
static __device__ __align__(256) __half g_m2_ci[NP * HID];
static __device__ __align__(256) __half g_m2_rh[NP * HID];
// CSR machinery
static __device__ int g_cnt[CNT_TOT];
static __device__ int g_fl[CNT_TOT];
static __device__ int g_rp_wr[NP + 1], g_rp_rw[NA + 1], g_rp_ci[NP + 1], g_rp_ht[NF + 1], g_rp_rh[NP + 1];
static __device__ int g_csr_wr[E_WR], g_csr_rw[E_RW], g_csr_ci[E_CI], g_csr_ht[E_HT], g_csr_rh[E_RH];
static __device__ int g_bsumA[5][128];
// summed weights / biases
static __device__ __align__(256) float g_wsumP[FIN * HID];
static __device__ __align__(256) float g_w2sum[HID * OUTF];
static __device__ __align__(256) float g_bsum1[HID];
static __device__ __align__(256) float g_bsum2[OUTF];

__constant__ int c_n[5] = {NP, NA, NP, NF, NP};
__constant__ int c_off[5] = {0, NP, NP + NA, NP + NA + NP, NP + NA + NP + NF};

__device__ __forceinline__ int* rp_of(int ty) {
    switch (ty) {
        case 0: return g_rp_wr;
        case 1: return g_rp_rw;
        case 2: return g_rp_ci;
        case 3: return g_rp_ht;
        default: return g_rp_rh;
    }
}
__device__ __forceinline__ int* csr_of(int ty) {
    switch (ty) {
        case 0: return g_csr_wr;
        case 1: return g_csr_rw;
        case 2: return g_csr_ci;
        case 3: return g_csr_ht;
        default: return g_csr_rh;
    }
}

// ---------------- fp16 MMA helpers ----------------
__device__ __forceinline__ uint32_t packh2(float a, float b) {
    __half2 h = __floats2half2_rn(a, b);
    return *reinterpret_cast<uint32_t*>(&h);
}

__device__ __forceinline__ void mma_f16(float c[4], uint32_t a0, uint32_t a1,
                                        uint32_t a2, uint32_t a3,
                                        uint32_t b0, uint32_t b1) {
    asm volatile("mma.sync.aligned.m16n8k16.row.col.f32.f16.f16.f32 "
                 "{%0,%1,%2,%3}, {%4,%5,%6,%7}, {%8,%9}, {%0,%1,%2,%3};"
                 : "+f"(c[0]), "+f"(c[1]), "+f"(c[2]), "+f"(c[3])
                 : "r"(a0), "r"(a1), "r"(a2), "r"(a3), "r"(b0), "r"(b1));
}

// ---------------- weight/bias prep ----------------
__global__ void prep_weights(const float* __restrict__ wr1a, const float* __restrict__ wr1b,
                             const float* __restrict__ wr1c,
                             const float* __restrict__ wr2a, const float* __restrict__ wr2b,
                             const float* __restrict__ wr2c,
                             const float* __restrict__ b1a, const float* __restrict__ b1b,
                             const float* __restrict__ b1c,
                             const float* __restrict__ b2a, const float* __restrict__ b2b,
                             const float* __restrict__ b2c) {
    int i = blockIdx.x * blockDim.x + threadIdx.x;
    if (i < FIN * HID) g_wsumP[i] = wr1a[i] + wr1b[i] + wr1c[i];
    if (i < HID * OUTF) g_w2sum[i] = wr2a[i] + wr2b[i] + wr2c[i];
    if (i < HID) g_bsum1[i] = b1a[i] + b1b[i] + b1c[i];
    if (i < OUTF) g_bsum2[i] = b2a[i] + b2b[i] + b2c[i];
}

// ---------------- CSR build ----------------
struct EJobs {
    const int* ei[5];
    int E[5];
    int bs[6];
};

__global__ void k_count_all(EJobs ep) {
    int b = blockIdx.x;
    int ty = 0;
    while (b >= ep.bs[ty + 1]) ++ty;
    int e = (b - ep.bs[ty]) * 256 + threadIdx.x;
    if (e >= ep.E[ty]) return;
    int d = __ldg(ep.ei[ty] + ep.E[ty] + e);
    atomicAdd(g_cnt + c_off[ty] + d, 1);
}

__global__ void k_blocksum_all() {
    __shared__ int s[256];
    int ty = blockIdx.y;
    int n = c_n[ty];
    int base = blockIdx.x * 1024;
    if (base >= n) { if (threadIdx.x == 0) g_bsumA[ty][blockIdx.x] = 0; return; }
    const int* c = g_cnt + c_off[ty];
    int t = threadIdx.x;
    int v = 0;
#pragma unroll
    for (int j = 0; j < 4; ++j) {
        int i = base + t * 4 + j;
        if (i < n) v += c[i];
    }
    s[t] = v;
    __syncthreads();
    for (int o = 128; o > 0; o >>= 1) {
        if (t < o) s[t] += s[t + o];
        __syncthreads();
    }
    if (t == 0) g_bsumA[ty][blockIdx.x] = s[0];
}

__global__ void k_scan_bsums_all() {
    __shared__ int s[256];
    int ty = blockIdx.x;
    int n = c_n[ty];
    int nb = (n + 1023) / 1024;
    int t = threadIdx.x;
    int v = (t < nb) ? g_bsumA[ty][t] : 0;
    s[t] = v;
    __syncthreads();
    for (int o = 1; o < 256; o <<= 1) {
        int x = (t >= o) ? s[t - o] : 0;
        __syncthreads();
        s[t] += x;
        __syncthreads();
    }
    if (t < nb) g_bsumA[ty][t] = s[t] - v;
    if (t == 0) rp_of(ty)[n] = s[255];
}

__global__ void k_scan_write_all() {
    __shared__ int s[256];
    int ty = blockIdx.y;
    int n = c_n[ty];
    int base = blockIdx.x * 1024;
    if (base >= n) return;
    const int* c = g_cnt + c_off[ty];
    int* rowptr = rp_of(ty);
    int* fill = g_fl + c_off[ty];
    int t = threadIdx.x;
    int loc[4];
    int v = 0;
#pragma unroll
    for (int j = 0; j < 4; ++j) {
        int i = base + t * 4 + j;
        loc[j] = v;
        v += (i < n) ? c[i] : 0;
    }
    s[t] = v;
    __syncthreads();
    for (int o = 1; o < 256; o <<= 1) {
        int x = (t >= o) ? s[t - o] : 0;
        __syncthreads();
        s[t] += x;
        __syncthreads();
    }
    int ex = s[t] - v;
    int off = g_bsumA[ty][blockIdx.x] + ex;
#pragma unroll
    for (int j = 0; j < 4; ++j) {
        int i = base + t * 4 + j;
        if (i < n) {
            int r = off + loc[j];
            rowptr[i] = r;
            fill[i] = r;
        }
    }
}

__global__ void k_fill_all(EJobs ep) {
    int b = blockIdx.x;
    int ty = 0;
    while (b >= ep.bs[ty + 1]) ++ty;
    int e = (b - ep.bs[ty]) * 256 + threadIdx.x;
    if (e >= ep.E[ty]) return;
    int s = __ldg(ep.ei[ty] + e);
    int d = __ldg(ep.ei[ty] + ep.E[ty] + e);
    int pos = atomicAdd(g_fl + c_off[ty] + d, 1);
    csr_of(ty)[pos] = s;
}

// ---------------- pull primitives (735-proven versions) ----------------
__device__ __forceinline__ void acc_h8_s(float acc[8], uint4 v, float s) {
    float2 f0 = __half22float2(*reinterpret_cast<const __half2*>(&v.x));
    float2 f1 = __half22float2(*reinterpret_cast<const __half2*>(&v.y));
    float2 f2 = __half22float2(*reinterpret_cast<const __half2*>(&v.z));
    float2 f3 = __half22float2(*reinterpret_cast<const __half2*>(&v.w));
    acc[0] += f0.x * s; acc[1] += f0.y * s;
    acc[2] += f1.x * s; acc[3] += f1.y * s;
    acc[4] += f2.x * s; acc[5] += f2.y * s;
    acc[6] += f3.x * s; acc[7] += f3.y * s;
}

__device__ __forceinline__ void acc_h8(float acc[8], uint4 v) {
    float2 f0 = __half22float2(*reinterpret_cast<const __half2*>(&v.x));
    float2 f1 = __half22float2(*reinterpret_cast<const __half2*>(&v.y));
    float2 f2 = __half22float2(*reinterpret_cast<const __half2*>(&v.z));
    float2 f3 = __half22float2(*reinterpret_cast<const __half2*>(&v.w));
    acc[0] += f0.x; acc[1] += f0.y;
    acc[2] += f1.x; acc[3] += f1.y;
    acc[4] += f2.x; acc[5] += f2.y;
    acc[6] += f3.x; acc[7] += f3.y;
}

__device__ __forceinline__ void shfl_reduce8(float acc[8]) {
#pragma unroll
    for (int i = 0; i < 8; ++i) {
        acc[i] += __shfl_xor_sync(0xffffffffu, acc[i], 8);
        acc[i] += __shfl_xor_sync(0xffffffffu, acc[i], 16);
    }
}

__device__ __forceinline__ uint4 pack_h8v(const float v[8]) {
    uint4 o;
    *reinterpret_cast<__half2*>(&o.x) = __floats2half2_rn(v[0], v[1]);
    *reinterpret_cast<__half2*>(&o.y) = __floats2half2_rn(v[2], v[3]);
    *reinterpret_cast<__half2*>(&o.z) = __floats2half2_rn(v[4], v[5]);
    *reinterpret_cast<__half2*>(&o.w) = __floats2half2_rn(v[6], v[7]);
    return o;
}

// branchless single-list pull: 4 clamp-indexed loads per iteration, scaled add.
__device__ __forceinline__ void pull1_scaled(const __half* __restrict__ feat,
                                             const int* __restrict__ csr,
                                             int beg, int end, int team, int c,
                                             float inv, float acc[8]) {
    int j = beg + team;
    while (j < end) {
        bool p1 = j + 4 < end, p2 = j + 8 < end, p3 = j + 12 < end;
        int i0 = j;
        int i1 = p1 ? j + 4 : i0;
        int i2 = p2 ? j + 8 : i0;
        int i3 = p3 ? j + 12 : i0;
        int s0 = __ldg(csr + i0);
        int s1 = __ldg(csr + i1);
        int s2 = __ldg(csr + i2);
        int s3 = __ldg(csr + i3);
        uint4 v0 = *(const uint4*)(feat + (size_t)s0 * HID + c * 8);
        uint4 v1 = *(const uint4*)(feat + (size_t)s1 * HID + c * 8);
        uint4 v2 = *(const uint4*)(feat + (size_t)s2 * HID + c * 8);
        uint4 v3 = *(const uint4*)(feat + (size_t)s3 * HID + c * 8);
        acc_h8_s(acc, v0, inv);
        acc_h8_s(acc, v1, p1 ? inv : 0.f);
        acc_h8_s(acc, v2, p2 ? inv : 0.f);
        acc_h8_s(acc, v3, p3 ? inv : 0.f);
        j += 16;
    }
}

// layer-1 paper: 3 edge lists fused in one loop (6 gathers/iter in flight),
// one scaled accumulator, one shfl tree. Node range [nodeBeg, nodeEnd).
__global__ void k_paper_warp(int nodeBeg, int nodeEnd) {
    int wg = nodeBeg + ((blockIdx.x * blockDim.x + threadIdx.x) >> 5);
    if (wg >= nodeEnd) return;
    int lane = threadIdx.x & 31;
    int team = lane >> 3, c = lane & 7;

    int bw = __ldg(g_rp_wr + wg), ew = __ldg(g_rp_wr + wg + 1);
    int bc = __ldg(g_rp_ci + wg), ec = __ldg(g_rp_ci + wg + 1);
    int br = __ldg(g_rp_rh + wg), er = __ldg(g_rp_rh + wg + 1);
    float invw = 1.f / fmaxf((float)(ew - bw), 1.f);
    float invc = 1.f / fmaxf((float)(ec - bc), 1.f);
    float invr = 1.f / fmaxf((float)(er - br), 1.f);

    float acc[8] = {};
    int jw = bw + team, jc = bc + team, jr = br + team;
    while (jw < ew || jc < ec || jr < er) {
        bool pw0 = jw < ew, pw1 = jw + 4 < ew;
        bool pc0 = jc < ec, pc1 = jc + 4 < ec;
        bool pr0 = jr < er, pr1 = jr + 4 < er;
        int iw0 = pw0 ? jw : 0, iw1 = pw1 ? jw + 4 : iw0;
        int ic0 = pc0 ? jc : 0, ic1 = pc1 ? jc + 4 : ic0;
        int ir0 = pr0 ? jr : 0, ir1 = pr1 ? jr + 4 : ir0;
        int sw0 = __ldg(g_csr_wr + iw0), sw1 = __ldg(g_csr_wr + iw1);
        int sc0 = __ldg(g_csr_ci + ic0), sc1 = __ldg(g_csr_ci + ic1);
        int sr0 = __ldg(g_csr_rh + ir0), sr1 = __ldg(g_csr_rh + ir1);
        uint4 vw0 = *(const uint4*)(g_hs_wr + (size_t)sw0 * HID + c * 8);
        uint4 vw1 = *(const uint4*)(g_hs_wr + (size_t)sw1 * HID + c * 8);
        uint4 vc0 = *(const uint4*)(g_hs_ci + (size_t)sc0 * HID + c * 8);
        uint4 vc1 = *(const uint4*)(g_hs_ci + (size_t)sc1 * HID + c * 8);
        uint4 vr0 = *(const uint4*)(g_hs_rh + (size_t)sr0 * HID + c * 8);
        uint4 vr1 = *(const uint4*)(g_hs_rh + (size_t)sr1 * HID + c * 8);
        acc_h8_s(acc, vw0, pw0 ? invw : 0.f);
        acc_h8_s(acc, vw1, pw1 ? invw : 0.f);
        acc_h8_s(acc, vc0, pc0 ? invc : 0.f);
        acc_h8_s(acc, vc1, pc1 ? invc : 0.f);
        acc_h8_s(acc, vr0, pr0 ? invr : 0.f);
        acc_h8_s(acc, vr1, pr1 ? invr : 0.f);
        jw += 8; jc += 8; jr += 8;
    }
    shfl_reduce8(acc);
    if (team == 0) {
        uint4 sv = *(const uint4*)(g_selfP + (size_t)wg * HID + c * 8);
        acc_h8(acc, sv);
        float o[8];
#pragma unroll
        for (int i = 0; i < 8; ++i)
            o[i] = fmaxf(acc[i] + g_bsum1[c * 8 + i], 0.f);
        *(uint4*)(g_p1h + (size_t)wg * HID + c * 8) = pack_h8v(o);
    }
}

// layer-1 author/field: 1 pull + self + bias + relu -> fp16 out
__global__ void k_af_warp(const __half* __restrict__ feat, const int* __restrict__ rowptr,
                          const int* __restrict__ csr, const __half* __restrict__ selfX,
                          const float* __restrict__ bias, __half* __restrict__ out, int n) {
    int wg = (blockIdx.x * blockDim.x + threadIdx.x) >> 5;
    if (wg >= n) return;
    int lane = threadIdx.x & 31;
    int team = lane >> 3, c = lane & 7;
    int beg = __ldg(rowptr + wg), end = __ldg(rowptr + wg + 1);
    float inv = 1.f / fmaxf((float)(end - beg), 1.f);
    float acc[8] = {};
    pull1_scaled(feat, csr, beg, end, team, c, inv, acc);
    shfl_reduce8(acc);
    if (team == 0) {
        uint4 sv = *(const uint4*)(selfX + (size_t)wg * HID + c * 8);
        acc_h8(acc, sv);
        float o[8];
#pragma unroll
        for (int i = 0; i < 8; ++i)
            o[i] = fmaxf(acc[i] + bias[c * 8 + i], 0.f);
        *(uint4*)(out + (size_t)wg * HID + c * 8) = pack_h8v(o);
    }
}

// layer-2 single pull -> fp16 mean buffer
__global__ void k_l2_warp(const __half* __restrict__ feat, const int* __restrict__ rowptr,
                          const int* __restrict__ csr, __half* __restrict__ out, int n) {
    int wg = (blockIdx.x * blockDim.x + threadIdx.x) >> 5;
    if (wg >= n) return;
    int lane = threadIdx.x & 31;
    int team = lane >> 3, c = lane & 7;
    int beg = __ldg(rowptr + wg), end = __ldg(rowptr + wg + 1);
    float inv = 1.f / fmaxf((float)(end - beg), 1.f);
    float acc[8] = {};
    pull1_scaled(feat, csr, beg, end, team, c, inv, acc);
    shfl_reduce8(acc);
    if (team == 0)
        *(uint4*)(out + (size_t)wg * HID + c * 8) = pack_h8v(acc);
}

// ---------------- fp16 HMMA GEMM: C[M,64](fp16) = A[M,128] @ B[128,64], batched ----------------
struct GemmBatch {
    const float* B[4];
    __half* C[4];
};

__global__ void gemm_f16_f128(const float* __restrict__ A, GemmBatch p, int M) {
    __shared__ uint32_t As[128 * 20];
    __shared__ uint32_t Bs[64 * 20];
    const float* __restrict__ Bp = p.B[blockIdx.y];
    __half* __restrict__ Cp = p.C[blockIdx.y];
    const int t = threadIdx.x;
    const int wid = t >> 5, lane = t & 31;
    const int g = lane >> 2, tg = lane & 3;
    const int rowBase = blockIdx.x * 128;
    const int wrow = wid * 16;

    float c[8][4] = {};

    for (int kb = 0; kb < 4; ++kb) {
#pragma unroll
        for (int j = 0; j < 4; ++j) {
            int idx = t + j * 256;
            int r = idx >> 3, q = idx & 7;
            int gr = rowBase + r;
            if (gr >= M) gr = M - 1;
            float4 av = *(const float4*)(A + (size_t)gr * FIN + kb * 32 + q * 4);
            As[r * 20 + q * 2 + 0] = packh2(av.x, av.y);
            As[r * 20 + q * 2 + 1] = packh2(av.z, av.w);
        }
#pragma unroll
        for (int j = 0; j < 4; ++j) {
            int idx = t + j * 256;
            int n = idx & 63, kh = idx >> 6;
            float v0 = Bp[(size_t)(kb * 32 + 2 * kh) * HID + n];
            float v1 = Bp[(size_t)(kb * 32 + 2 * kh + 1) * HID + n];
            Bs[n * 20 + kh] = packh2(v0, v1);
        }
        __syncthreads();
#pragma unroll
        for (int ks = 0; ks < 2; ++ks) {
            int kh0 = ks * 8;
            uint32_t a0 = As[(wrow + g) * 20 + kh0 + tg];
            uint32_t a1 = As[(wrow + g + 8) * 20 + kh0 + tg];
            uint32_t a2 = As[(wrow + g) * 20 + kh0 + tg + 4];
            uint32_t a3 = As[(wrow + g + 8) * 20 + kh0 + tg + 4];
#pragma unroll
            for (int nt = 0; nt < 8; ++nt) {
                int n = nt * 8 + g;
                uint32_t b0 = Bs[n * 20 + kh0 + tg];
                uint32_t b1 = Bs[n * 20 + kh0 + tg + 4];
                mma_f16(c[nt], a0, a1, a2, a3, b0, b1);
            }
        }
        __syncthreads();
    }

    int r0 = rowBase + wrow + g, r1 = r0 + 8;
#pragma unroll
    for (int nt = 0; nt < 8; ++nt) {
        int col = nt * 8 + tg * 2;
        if (r0 < M)
            *reinterpret_cast<__half2*>(Cp + (size_t)r0 * HID + col) = __floats2half2_rn(c[nt][0], c[nt][1]);
        if (r1 < M)
            *reinterpret_cast<__half2*>(Cp + (size_t)r1 * HID + col) = __floats2half2_rn(c[nt][2], c[nt][3]);
    }
}

// ---------------- fp16 HMMA output GEMM: fp16 A inputs, fp32 out ----------------
__global__ void gemm_out_f16(const __half* __restrict__ A0, const __half* __restrict__ A1,
                             const __half* __restrict__ A2, const __half* __restrict__ A3,
                             const float* __restrict__ B0, const float* __restrict__ B1,
                             const float* __restrict__ B2, const float* __restrict__ B3,
                             float* __restrict__ C, int M) {
    __shared__ uint32_t As[128 * 20];
    __shared__ uint32_t Bs[64 * 20];
    const int t = threadIdx.x;
    const int wid = t >> 5, lane = t & 31;
    const int g = lane >> 2, tg = lane & 3;
    const int rowBase = blockIdx.x * 128;
    const int colBase = blockIdx.y * 64;
    const int wrow = wid * 16;

    const __half* Aps[4] = {A0, A1, A2, A3};
    const float* Bps[4] = {B0, B1, B2, B3};

    float c[8][4] = {};

    for (int m = 0; m < 4; ++m) {
        const __half* __restrict__ Ap = Aps[m];
        const float* __restrict__ Bp = Bps[m];
        for (int kb = 0; kb < 2; ++kb) {
#pragma unroll
            for (int j = 0; j < 2; ++j) {
                int idx = t + j * 256;
                int r = idx >> 2, q = idx & 3;
                int gr = rowBase + r;
                if (gr >= M) gr = M - 1;
                uint4 hv = *(const uint4*)(Ap + (size_t)gr * HID + kb * 32 + q * 8);
                uint32_t* d = &As[r * 20 + q * 4];
                d[0] = hv.x; d[1] = hv.y; d[2] = hv.z; d[3] = hv.w;
            }
#pragma unroll
            for (int j = 0; j < 4; ++j) {
                int idx = t + j * 256;
                int n = idx & 63, kh = idx >> 6;
                int col = colBase + n;
                float v0 = 0.f, v1 = 0.f;
                if (col < OUTF) {
                    v0 = Bp[(size_t)(kb * 32 + 2 * kh) * OUTF + col];
                    v1 = Bp[(size_t)(kb * 32 + 2 * kh + 1) * OUTF + col];
                }
                Bs[n * 20 + kh] = packh2(v0, v1);
            }
            __syncthreads();
#pragma unroll
            for (int ks = 0; ks < 2; ++ks) {
                int kh0 = ks * 8;
                uint32_t a0 = As[(wrow + g) * 20 + kh0 + tg];
                uint32_t a1 = As[(wrow + g + 8) * 20 + kh0 + tg];
                uint32_t a2 = As[(wrow + g) * 20 + kh0 + tg + 4];
                uint32_t a3 = As[(wrow + g + 8) * 20 + kh0 + tg + 4];
#pragma unroll
                for (int nt = 0; nt < 8; ++nt) {
                    int n = nt * 8 + g;
                    uint32_t b0 = Bs[n * 20 + kh0 + tg];
                    uint32_t b1 = Bs[n * 20 + kh0 + tg + 4];
                    mma_f16(c[nt], a0, a1, a2, a3, b0, b1);
                }
            }
            __syncthreads();
        }
    }

    int r0 = rowBase + wrow + g, r1 = r0 + 8;
#pragma unroll
    for (int nt = 0; nt < 8; ++nt) {
        int col = colBase + nt * 8 + tg * 2;
        if (col < OUTF) {
            float bia = g_bsum2[col];
            if (r0 < M) C[(size_t)r0 * OUTF + col] = c[nt][0] + bia;
            if (r1 < M) C[(size_t)r1 * OUTF + col] = c[nt][2] + bia;
        }
        if (col + 1 < OUTF) {
            float bib = g_bsum2[col + 1];
            if (r0 < M) C[(size_t)r0 * OUTF + col + 1] = c[nt][1] + bib;
            if (r1 < M) C[(size_t)r1 * OUTF + col + 1] = c[nt][3] + bib;
        }
    }
}

// ---------------- host launcher ----------------
static inline void* sym(const void* s) {
    void* p = nullptr;
    cudaGetSymbolAddress(&p, s);
    return p;
}

extern "C" void kernel_launch(void* const* d_in, const int* in_sizes, int n_in,
                              void* d_out, int out_size) {
    static cudaStream_t s1 = nullptr, s2 = nullptr;
    static cudaEvent_t ev0 = nullptr, ev1 = nullptr, ev2 = nullptr, ev3 = nullptr,
                       ev4 = nullptr, evPb = nullptr, evPc = nullptr;
    if (s1 == nullptr) {
        cudaStreamCreateWithFlags(&s1, cudaStreamNonBlocking);
        cudaStreamCreateWithFlags(&s2, cudaStreamNonBlocking);
        cudaEventCreateWithFlags(&ev0, cudaEventDisableTiming);
        cudaEventCreateWithFlags(&ev1, cudaEventDisableTiming);
        cudaEventCreateWithFlags(&ev2, cudaEventDisableTiming);
        cudaEventCreateWithFlags(&ev3, cudaEventDisableTiming);
        cudaEventCreateWithFlags(&ev4, cudaEventDisableTiming);
        cudaEventCreateWithFlags(&evPb, cudaEventDisableTiming);
        cudaEventCreateWithFlags(&evPc, cudaEventDisableTiming);
    }

    const float* x_paper  = (const float*)d_in[0];
    const float* x_author = (const float*)d_in[1];
    const float* x_field  = (const float*)d_in[2];
    const int* ei_wr = (const int*)d_in[3];
    const int* ei_rw = (const int*)d_in[4];
    const int* ei_ci = (const int*)d_in[5];
    const int* ei_ht = (const int*)d_in[6];
    const int* ei_rh = (const int*)d_in[7];
    const int nE_wr = in_sizes[3] / 2;
    const int nE_rw = in_sizes[4] / 2;
    const int nE_ci = in_sizes[5] / 2;
    const int nE_ht = in_sizes[6] / 2;
    const int nE_rh = in_sizes[7] / 2;

    const float* wl1_wr = (const float*)d_in[8];
    const float* wr1_wr = (const float*)d_in[9];
    const float* b1_wr  = (const float*)d_in[10];
    const float* wl1_rw = (const float*)d_in[11];
    const float* wr1_rw = (const float*)d_in[12];
    const float* b1_rw  = (const float*)d_in[13];
    const float* wl1_ci = (const float*)d_in[14];
    const float* wr1_ci = (const float*)d_in[15];
    const float* b1_ci  = (const float*)d_in[16];
    const float* wl1_ht = (const float*)d_in[17];
    const float* wr1_ht = (const float*)d_in[18];
    const float* b1_ht  = (const float*)d_in[19];
    const float* wl1_rh = (const float*)d_in[20];
    const float* wr1_rh = (const float*)d_in[21];
    const float* b1_rh  = (const float*)d_in[22];
    const float* wl2_wr = (const float*)d_in[23];
    const float* wr2_wr = (const float*)d_in[24];
    const float* b2_wr  = (const float*)d_in[25];
    const float* wl2_ci = (const float*)d_in[26];
    const float* wr2_ci = (const float*)d_in[27];
    const float* b2_ci  = (const float*)d_in[28];
    const float* wl2_rh = (const float*)d_in[29];
    const float* wr2_rh = (const float*)d_in[30];
    const float* b2_rh  = (const float*)d_in[31];

    float* out = (float*)d_out;

    __half* hs_wr = (__half*)sym(g_hs_wr);
    __half* hs_rw = (__half*)sym(g_hs_rw);
    __half* hs_ci = (__half*)sym(g_hs_ci);
    __half* hs_ht = (__half*)sym(g_hs_ht);
    __half* hs_rh = (__half*)sym(g_hs_rh);
    __half* selfP = (__half*)sym(g_selfP);
    __half* selfA = (__half*)sym(g_selfA);
    __half* selfF = (__half*)sym(g_selfF);
    __half* a1h = (__half*)sym(g_a1h);
    __half* f1h = (__half*)sym(g_f1h);
    __half* p1h = (__half*)sym(g_p1h);
    __half* m2_wr = (__half*)sym(g_m2_wr);
    __half* m2_ci = (__half*)sym(g_m2_ci);
    __half* m2_rh = (__half*)sym(g_m2_rh);
    int* cnt = (int*)sym(g_cnt);
    int* rp_wr = (int*)sym(g_rp_wr);
    int* rp_rw = (int*)sym(g_rp_rw);
    int* rp_ci = (int*)sym(g_rp_ci);
    int* rp_ht = (int*)sym(g_rp_ht);
    int* rp_rh = (int*)sym(g_rp_rh);
    int* csr_wr = (int*)sym(g_csr_wr);
    int* csr_rw = (int*)sym(g_csr_rw);
    int* csr_ci = (int*)sym(g_csr_ci);
    int* csr_ht = (int*)sym(g_csr_ht);
    int* csr_rh = (int*)sym(g_csr_rh);
    float* wsumP = (float*)sym(g_wsumP);
    float* w2sum = (float*)sym(g_w2sum);

    // ---- fork: s1 does weight prep + layer-1 GEMMs ----
    cudaEventRecord(ev0, 0);
    cudaStreamWaitEvent(s1, ev0, 0);

    prep_weights<<<(HID * OUTF + 255) / 256, 256, 0, s1>>>(
        wr1_wr, wr1_ci, wr1_rh, wr2_wr, wr2_ci, wr2_rh,
        b1_wr, b1_ci, b1_rh, b2_wr, b2_ci, b2_rh);

    const int gP = (NP + 127) / 128, gA = (NA + 127) / 128, gF = (NF + 127) / 128;
    {
        GemmBatch bp;
        bp.B[0] = wl1_rw; bp.C[0] = hs_rw;
        bp.B[1] = wl1_ci; bp.C[1] = hs_ci;
        bp.B[2] = wl1_ht; bp.C[2] = hs_ht;
        bp.B[3] = wsumP;  bp.C[3] = selfP;
        gemm_f16_f128<<<dim3(gP, 4), 256, 0, s1>>>(x_paper, bp, NP);
        GemmBatch ba;
        ba.B[0] = wl1_wr; ba.C[0] = hs_wr;
        ba.B[1] = wr1_rw; ba.C[1] = selfA;
        ba.B[2] = wl1_wr; ba.C[2] = hs_wr;
        ba.B[3] = wl1_wr; ba.C[3] = hs_wr;
        gemm_f16_f128<<<dim3(gA, 2), 256, 0, s1>>>(x_author, ba, NA);
        GemmBatch bf;
        bf.B[0] = wl1_rh; bf.C[0] = hs_rh;
        bf.B[1] = wr1_ht; bf.C[1] = selfF;
        bf.B[2] = wl1_rh; bf.C[2] = hs_rh;
        bf.B[3] = wl1_rh; bf.C[3] = hs_rh;
        gemm_f16_f128<<<dim3(gF, 2), 256, 0, s1>>>(x_field, bf, NF);
    }
    cudaEventRecord(ev1, s1);

    // ---- stream 0: CSR build ----
    cudaMemsetAsync(cnt, 0, sizeof(int) * CNT_TOT, 0);

    EJobs ep;
    ep.ei[0] = ei_wr; ep.E[0] = nE_wr;
    ep.ei[1] = ei_rw; ep.E[1] = nE_rw;
    ep.ei[2] = ei_ci; ep.E[2] = nE_ci;
    ep.ei[3] = ei_ht; ep.E[3] = nE_ht;
    ep.ei[4] = ei_rh; ep.E[4] = nE_rh;
    ep.bs[0] = 0;
    for (int i = 0; i < 5; ++i) ep.bs[i + 1] = ep.bs[i] + (ep.E[i] + 255) / 256;

    k_count_all<<<ep.bs[5], 256>>>(ep);
    k_blocksum_all<<<dim3((NP + 1023) / 1024, 5), 256>>>();
    k_scan_bsums_all<<<5, 256>>>();
    k_scan_write_all<<<dim3((NP + 1023) / 1024, 5), 256>>>();
    k_fill_all<<<ep.bs[5], 256>>>(ep);
    cudaEventRecord(ev2, 0);

    auto wgr = [](int n) { return (n * 32 + 255) / 256; };

    // paper node split: 3 balanced chunks
    const int P1 = NP / 3;            // 33333
    const int P2 = 2 * NP / 3;        // 66666

    // ---- stream 0: paper chunk 0, then (after chunks 1,2) l2_ci ----
    cudaStreamWaitEvent(0, ev1, 0);      // needs hs_* from s1
    k_paper_warp<<<wgr(P1), 256>>>(0, P1);

    // ---- s1: paper chunk 1, then author chain ----
    cudaStreamWaitEvent(s1, ev2, 0);     // needs CSR from stream 0 (hs_* in-stream)
    k_paper_warp<<<wgr(P2 - P1), 256, 0, s1>>>(P1, P2);
    cudaEventRecord(evPb, s1);
    k_af_warp<<<wgr(NA), 256, 0, s1>>>(hs_rw, rp_rw, csr_rw, selfA, b1_rw, a1h, NA);
    k_l2_warp<<<wgr(NP), 256, 0, s1>>>(a1h, rp_wr, csr_wr, m2_wr, NP);
    cudaEventRecord(ev3, s1);

    // ---- s2: paper chunk 2, then field chain ----
    cudaStreamWaitEvent(s2, ev1, 0);
    cudaStreamWaitEvent(s2, ev2, 0);
    k_paper_warp<<<wgr(NP - P2), 256, 0, s2>>>(P2, NP);
    cudaEventRecord(evPc, s2);
    k_af_warp<<<wgr(NF), 256, 0, s2>>>(hs_ht, rp_ht, csr_ht, selfF, b1_ht, f1h, NF);
    k_l2_warp<<<wgr(NP), 256, 0, s2>>>(f1h, rp_rh, csr_rh, m2_rh, NP);
    cudaEventRecord(ev4, s2);

    // ---- stream 0: l2_ci (needs complete p1h) ----
    cudaStreamWaitEvent(0, evPb, 0);
    cudaStreamWaitEvent(0, evPc, 0);
    k_l2_warp<<<wgr(NP), 256>>>(p1h, rp_ci, csr_ci, m2_ci, NP);

    // ---- join + output GEMM ----
    cudaStreamWaitEvent(0, ev3, 0);
    cudaStreamWaitEvent(0, ev4, 0);
    dim3 g2(gP, (OUTF + 63) / 64);
    gemm_out_f16<<<g2, 256>>>(m2_wr, m2_ci, m2_rh, p1h,
                              wl2_wr, wl2_ci, wl2_rh, w2sum,
                              out, NP);
}

// round 16
// speedup vs baseline: 1.2480x; 1.0056x over previous
#include <cuda_runtime.h>
#include <cuda_fp16.h>
#include <cstdint>

#define NP 100000
#define NA 100000
#define NF 50000
#define FIN 128
#define HID 64
#define OUTF 349

#define E_WR 1000000
#define E_RW 1000000
#define E_CI 2000000
#define E_HT 1000000
#define E_RH 1000000

#define CNT_TOT (NP + NA + NP + NF + NP)   // 450000

// ---------------- scratch ----------------
static __device__ __align__(256) __half g_hs_wr[NA * HID];
static __device__ __align__(256) __half g_hs_rw[NP * HID];
static __device__ __align__(256) __half g_hs_ci[NP * HID];
static __device__ __align__(256) __half g_hs_ht[NP * HID];
static __device__ __align__(256) __half g_hs_rh[NF * HID];
static __device__ __align__(256) __half g_selfP[NP * HID];
static __device__ __align__(256) __half g_selfA[NA * HID];
static __device__ __align__(256) __half g_selfF[NF * HID];
static __device__ __align__(256) __half g_p1h[NP * HID];
static __device__ __align__(256) __half g_a1h[NA * HID];
static __device__ __align__(256) __half g_f1h[NF * HID];
static __device__ __align__(256) __half g_m2_wr[NP * HID];
static __device__ __align__(256) __half g_m2_ci[NP * HID];
static __device__ __align__(256) __half g_m2_rh[NP * HID];
// CSR machinery
static __device__ int g_cnt[CNT_TOT];
static __device__ int g_fl[CNT_TOT];
static __device__ int g_rp_wr[NP + 1], g_rp_rw[NA + 1], g_rp_ci[NP + 1], g_rp_ht[NF + 1], g_rp_rh[NP + 1];
static __device__ int g_csr_wr[E_WR], g_csr_rw[E_RW], g_csr_ci[E_CI], g_csr_ht[E_HT], g_csr_rh[E_RH];
static __device__ int g_bsumA[5][128];
// summed weights / biases
static __device__ __align__(256) float g_wsumP[FIN * HID];
static __device__ __align__(256) float g_w2sum[HID * OUTF];
static __device__ __align__(256) float g_bsum1[HID];
static __device__ __align__(256) float g_bsum2[OUTF];

__constant__ int c_n[5] = {NP, NA, NP, NF, NP};
__constant__ int c_off[5] = {0, NP, NP + NA, NP + NA + NP, NP + NA + NP + NF};

__device__ __forceinline__ int* rp_of(int ty) {
    switch (ty) {
        case 0: return g_rp_wr;
        case 1: return g_rp_rw;
        case 2: return g_rp_ci;
        case 3: return g_rp_ht;
        default: return g_rp_rh;
    }
}
__device__ __forceinline__ int* csr_of(int ty) {
    switch (ty) {
        case 0: return g_csr_wr;
        case 1: return g_csr_rw;
        case 2: return g_csr_ci;
        case 3: return g_csr_ht;
        default: return g_csr_rh;
    }
}

// ---------------- fp16 MMA helpers ----------------
__device__ __forceinline__ uint32_t packh2(float a, float b) {
    __half2 h = __floats2half2_rn(a, b);
    return *reinterpret_cast<uint32_t*>(&h);
}

__device__ __forceinline__ void mma_f16(float c[4], uint32_t a0, uint32_t a1,
                                        uint32_t a2, uint32_t a3,
                                        uint32_t b0, uint32_t b1) {
    asm volatile("mma.sync.aligned.m16n8k16.row.col.f32.f16.f16.f32 "
                 "{%0,%1,%2,%3}, {%4,%5,%6,%7}, {%8,%9}, {%0,%1,%2,%3};"
                 : "+f"(c[0]), "+f"(c[1]), "+f"(c[2]), "+f"(c[3])
                 : "r"(a0), "r"(a1), "r"(a2), "r"(a3), "r"(b0), "r"(b1));
}

// ---------------- weight/bias prep ----------------
__global__ void prep_weights(const float* __restrict__ wr1a, const float* __restrict__ wr1b,
                             const float* __restrict__ wr1c,
                             const float* __restrict__ wr2a, const float* __restrict__ wr2b,
                             const float* __restrict__ wr2c,
                             const float* __restrict__ b1a, const float* __restrict__ b1b,
                             const float* __restrict__ b1c,
                             const float* __restrict__ b2a, const float* __restrict__ b2b,
                             const float* __restrict__ b2c) {
    int i = blockIdx.x * blockDim.x + threadIdx.x;
    if (i < FIN * HID) g_wsumP[i] = wr1a[i] + wr1b[i] + wr1c[i];
    if (i < HID * OUTF) g_w2sum[i] = wr2a[i] + wr2b[i] + wr2c[i];
    if (i < HID) g_bsum1[i] = b1a[i] + b1b[i] + b1c[i];
    if (i < OUTF) g_bsum2[i] = b2a[i] + b2b[i] + b2c[i];
}

// ---------------- CSR build ----------------
struct EJobs {
    const int* ei[5];
    int E[5];
    int bs[6];
};

__global__ void k_count_all(EJobs ep) {
    int b = blockIdx.x;
    int ty = 0;
    while (b >= ep.bs[ty + 1]) ++ty;
    int e = (b - ep.bs[ty]) * 256 + threadIdx.x;
    if (e >= ep.E[ty]) return;
    int d = __ldg(ep.ei[ty] + ep.E[ty] + e);
    atomicAdd(g_cnt + c_off[ty] + d, 1);
}

__global__ void k_blocksum_all() {
    __shared__ int s[256];
    int ty = blockIdx.y;
    int n = c_n[ty];
    int base = blockIdx.x * 1024;
    if (base >= n) { if (threadIdx.x == 0) g_bsumA[ty][blockIdx.x] = 0; return; }
    const int* c = g_cnt + c_off[ty];
    int t = threadIdx.x;
    int v = 0;
#pragma unroll
    for (int j = 0; j < 4; ++j) {
        int i = base + t * 4 + j;
        if (i < n) v += c[i];
    }
    s[t] = v;
    __syncthreads();
    for (int o = 128; o > 0; o >>= 1) {
        if (t < o) s[t] += s[t + o];
        __syncthreads();
    }
    if (t == 0) g_bsumA[ty][blockIdx.x] = s[0];
}

__global__ void k_scan_bsums_all() {
    __shared__ int s[256];
    int ty = blockIdx.x;
    int n = c_n[ty];
    int nb = (n + 1023) / 1024;
    int t = threadIdx.x;
    int v = (t < nb) ? g_bsumA[ty][t] : 0;
    s[t] = v;
    __syncthreads();
    for (int o = 1; o < 256; o <<= 1) {
        int x = (t >= o) ? s[t - o] : 0;
        __syncthreads();
        s[t] += x;
        __syncthreads();
    }
    if (t < nb) g_bsumA[ty][t] = s[t] - v;
    if (t == 0) rp_of(ty)[n] = s[255];
}

__global__ void k_scan_write_all() {
    __shared__ int s[256];
    int ty = blockIdx.y;
    int n = c_n[ty];
    int base = blockIdx.x * 1024;
    if (base >= n) return;
    const int* c = g_cnt + c_off[ty];
    int* rowptr = rp_of(ty);
    int* fill = g_fl + c_off[ty];
    int t = threadIdx.x;
    int loc[4];
    int v = 0;
#pragma unroll
    for (int j = 0; j < 4; ++j) {
        int i = base + t * 4 + j;
        loc[j] = v;
        v += (i < n) ? c[i] : 0;
    }
    s[t] = v;
    __syncthreads();
    for (int o = 1; o < 256; o <<= 1) {
        int x = (t >= o) ? s[t - o] : 0;
        __syncthreads();
        s[t] += x;
        __syncthreads();
    }
    int ex = s[t] - v;
    int off = g_bsumA[ty][blockIdx.x] + ex;
#pragma unroll
    for (int j = 0; j < 4; ++j) {
        int i = base + t * 4 + j;
        if (i < n) {
            int r = off + loc[j];
            rowptr[i] = r;
            fill[i] = r;
        }
    }
}

__global__ void k_fill_all(EJobs ep) {
    int b = blockIdx.x;
    int ty = 0;
    while (b >= ep.bs[ty + 1]) ++ty;
    int e = (b - ep.bs[ty]) * 256 + threadIdx.x;
    if (e >= ep.E[ty]) return;
    int s = __ldg(ep.ei[ty] + e);
    int d = __ldg(ep.ei[ty] + ep.E[ty] + e);
    int pos = atomicAdd(g_fl + c_off[ty] + d, 1);
    csr_of(ty)[pos] = s;
}

// ---------------- pull primitives ----------------
__device__ __forceinline__ void acc_h8_s(float acc[8], uint4 v, float s) {
    float2 f0 = __half22float2(*reinterpret_cast<const __half2*>(&v.x));
    float2 f1 = __half22float2(*reinterpret_cast<const __half2*>(&v.y));
    float2 f2 = __half22float2(*reinterpret_cast<const __half2*>(&v.z));
    float2 f3 = __half22float2(*reinterpret_cast<const __half2*>(&v.w));
    acc[0] += f0.x * s; acc[1] += f0.y * s;
    acc[2] += f1.x * s; acc[3] += f1.y * s;
    acc[4] += f2.x * s; acc[5] += f2.y * s;
    acc[6] += f3.x * s; acc[7] += f3.y * s;
}

__device__ __forceinline__ void acc_h8(float acc[8], uint4 v) {
    float2 f0 = __half22float2(*reinterpret_cast<const __half2*>(&v.x));
    float2 f1 = __half22float2(*reinterpret_cast<const __half2*>(&v.y));
    float2 f2 = __half22float2(*reinterpret_cast<const __half2*>(&v.z));
    float2 f3 = __half22float2(*reinterpret_cast<const __half2*>(&v.w));
    acc[0] += f0.x; acc[1] += f0.y;
    acc[2] += f1.x; acc[3] += f1.y;
    acc[4] += f2.x; acc[5] += f2.y;
    acc[6] += f3.x; acc[7] += f3.y;
}

__device__ __forceinline__ void shfl_reduce8(float acc[8]) {
#pragma unroll
    for (int i = 0; i < 8; ++i) {
        acc[i] += __shfl_xor_sync(0xffffffffu, acc[i], 8);
        acc[i] += __shfl_xor_sync(0xffffffffu, acc[i], 16);
    }
}

__device__ __forceinline__ uint4 pack_h8v(const float v[8]) {
    uint4 o;
    *reinterpret_cast<__half2*>(&o.x) = __floats2half2_rn(v[0], v[1]);
    *reinterpret_cast<__half2*>(&o.y) = __floats2half2_rn(v[2], v[3]);
    *reinterpret_cast<__half2*>(&o.z) = __floats2half2_rn(v[4], v[5]);
    *reinterpret_cast<__half2*>(&o.w) = __floats2half2_rn(v[6], v[7]);
    return o;
}

// branchless single-list pull: 4 clamp-indexed loads per iteration, scaled add.
__device__ __forceinline__ void pull1_scaled(const __half* __restrict__ feat,
                                             const int* __restrict__ csr,
                                             int beg, int end, int team, int c,
                                             float inv, float acc[8]) {
    int j = beg + team;
    while (j < end) {
        bool p1 = j + 4 < end, p2 = j + 8 < end, p3 = j + 12 < end;
        int i0 = j;
        int i1 = p1 ? j + 4 : i0;
        int i2 = p2 ? j + 8 : i0;
        int i3 = p3 ? j + 12 : i0;
        int s0 = __ldg(csr + i0);
        int s1 = __ldg(csr + i1);
        int s2 = __ldg(csr + i2);
        int s3 = __ldg(csr + i3);
        uint4 v0 = *(const uint4*)(feat + (size_t)s0 * HID + c * 8);
        uint4 v1 = *(const uint4*)(feat + (size_t)s1 * HID + c * 8);
        uint4 v2 = *(const uint4*)(feat + (size_t)s2 * HID + c * 8);
        uint4 v3 = *(const uint4*)(feat + (size_t)s3 * HID + c * 8);
        acc_h8_s(acc, v0, inv);
        acc_h8_s(acc, v1, p1 ? inv : 0.f);
        acc_h8_s(acc, v2, p2 ? inv : 0.f);
        acc_h8_s(acc, v3, p3 ? inv : 0.f);
        j += 16;
    }
}

// layer-1 paper: 3 edge lists fused in one loop (6 gathers/iter in flight),
// one scaled accumulator, one shfl tree.
__global__ void k_paper_warp() {
    int wg = (blockIdx.x * blockDim.x + threadIdx.x) >> 5;
    if (wg >= NP) return;
    int lane = threadIdx.x & 31;
    int team = lane >> 3, c = lane & 7;

    int bw = __ldg(g_rp_wr + wg), ew = __ldg(g_rp_wr + wg + 1);
    int bc = __ldg(g_rp_ci + wg), ec = __ldg(g_rp_ci + wg + 1);
    int br = __ldg(g_rp_rh + wg), er = __ldg(g_rp_rh + wg + 1);
    float invw = 1.f / fmaxf((float)(ew - bw), 1.f);
    float invc = 1.f / fmaxf((float)(ec - bc), 1.f);
    float invr = 1.f / fmaxf((float)(er - br), 1.f);

    float acc[8] = {};
    int jw = bw + team, jc = bc + team, jr = br + team;
    while (jw < ew || jc < ec || jr < er) {
        bool pw0 = jw < ew, pw1 = jw + 4 < ew;
        bool pc0 = jc < ec, pc1 = jc + 4 < ec;
        bool pr0 = jr < er, pr1 = jr + 4 < er;
        int iw0 = pw0 ? jw : 0, iw1 = pw1 ? jw + 4 : iw0;
        int ic0 = pc0 ? jc : 0, ic1 = pc1 ? jc + 4 : ic0;
        int ir0 = pr0 ? jr : 0, ir1 = pr1 ? jr + 4 : ir0;
        int sw0 = __ldg(g_csr_wr + iw0), sw1 = __ldg(g_csr_wr + iw1);
        int sc0 = __ldg(g_csr_ci + ic0), sc1 = __ldg(g_csr_ci + ic1);
        int sr0 = __ldg(g_csr_rh + ir0), sr1 = __ldg(g_csr_rh + ir1);
        uint4 vw0 = *(const uint4*)(g_hs_wr + (size_t)sw0 * HID + c * 8);
        uint4 vw1 = *(const uint4*)(g_hs_wr + (size_t)sw1 * HID + c * 8);
        uint4 vc0 = *(const uint4*)(g_hs_ci + (size_t)sc0 * HID + c * 8);
        uint4 vc1 = *(const uint4*)(g_hs_ci + (size_t)sc1 * HID + c * 8);
        uint4 vr0 = *(const uint4*)(g_hs_rh + (size_t)sr0 * HID + c * 8);
        uint4 vr1 = *(const uint4*)(g_hs_rh + (size_t)sr1 * HID + c * 8);
        acc_h8_s(acc, vw0, pw0 ? invw : 0.f);
        acc_h8_s(acc, vw1, pw1 ? invw : 0.f);
        acc_h8_s(acc, vc0, pc0 ? invc : 0.f);
        acc_h8_s(acc, vc1, pc1 ? invc : 0.f);
        acc_h8_s(acc, vr0, pr0 ? invr : 0.f);
        acc_h8_s(acc, vr1, pr1 ? invr : 0.f);
        jw += 8; jc += 8; jr += 8;
    }
    shfl_reduce8(acc);
    if (team == 0) {
        uint4 sv = *(const uint4*)(g_selfP + (size_t)wg * HID + c * 8);
        acc_h8(acc, sv);
        float o[8];
#pragma unroll
        for (int i = 0; i < 8; ++i)
            o[i] = fmaxf(acc[i] + g_bsum1[c * 8 + i], 0.f);
        *(uint4*)(g_p1h + (size_t)wg * HID + c * 8) = pack_h8v(o);
    }
}

// layer-1 author/field: 1 pull + self + bias + relu -> fp16 out
__global__ void k_af_warp(const __half* __restrict__ feat, const int* __restrict__ rowptr,
                          const int* __restrict__ csr, const __half* __restrict__ selfX,
                          const float* __restrict__ bias, __half* __restrict__ out, int n) {
    int wg = (blockIdx.x * blockDim.x + threadIdx.x) >> 5;
    if (wg >= n) return;
    int lane = threadIdx.x & 31;
    int team = lane >> 3, c = lane & 7;
    int beg = __ldg(rowptr + wg), end = __ldg(rowptr + wg + 1);
    float inv = 1.f / fmaxf((float)(end - beg), 1.f);
    float acc[8] = {};
    pull1_scaled(feat, csr, beg, end, team, c, inv, acc);
    shfl_reduce8(acc);
    if (team == 0) {
        uint4 sv = *(const uint4*)(selfX + (size_t)wg * HID + c * 8);
        acc_h8(acc, sv);
        float o[8];
#pragma unroll
        for (int i = 0; i < 8; ++i)
            o[i] = fmaxf(acc[i] + bias[c * 8 + i], 0.f);
        *(uint4*)(out + (size_t)wg * HID + c * 8) = pack_h8v(o);
    }
}

// layer-2 single pull -> fp16 mean buffer
__global__ void k_l2_warp(const __half* __restrict__ feat, const int* __restrict__ rowptr,
                          const int* __restrict__ csr, __half* __restrict__ out, int n) {
    int wg = (blockIdx.x * blockDim.x + threadIdx.x) >> 5;
    if (wg >= n) return;
    int lane = threadIdx.x & 31;
    int team = lane >> 3, c = lane & 7;
    int beg = __ldg(rowptr + wg), end = __ldg(rowptr + wg + 1);
    float inv = 1.f / fmaxf((float)(end - beg), 1.f);
    float acc[8] = {};
    pull1_scaled(feat, csr, beg, end, team, c, inv, acc);
    shfl_reduce8(acc);
    if (team == 0)
        *(uint4*)(out + (size_t)wg * HID + c * 8) = pack_h8v(acc);
}

// ---------------- fp16 HMMA GEMM: C[M,64](fp16) = A[M,128] @ B[128,64], batched ----------------
struct GemmBatch {
    const float* B[4];
    __half* C[4];
};

__global__ void gemm_f16_f128(const float* __restrict__ A, GemmBatch p, int M) {
    __shared__ uint32_t As[128 * 20];
    __shared__ uint32_t Bs[64 * 20];
    const float* __restrict__ Bp = p.B[blockIdx.y];
    __half* __restrict__ Cp = p.C[blockIdx.y];
    const int t = threadIdx.x;
    const int wid = t >> 5, lane = t & 31;
    const int g = lane >> 2, tg = lane & 3;
    const int rowBase = blockIdx.x * 128;
    const int wrow = wid * 16;

    float c[8][4] = {};

    for (int kb = 0; kb < 4; ++kb) {
#pragma unroll
        for (int j = 0; j < 4; ++j) {
            int idx = t + j * 256;
            int r = idx >> 3, q = idx & 7;
            int gr = rowBase + r;
            if (gr >= M) gr = M - 1;
            float4 av = *(const float4*)(A + (size_t)gr * FIN + kb * 32 + q * 4);
            As[r * 20 + q * 2 + 0] = packh2(av.x, av.y);
            As[r * 20 + q * 2 + 1] = packh2(av.z, av.w);
        }
#pragma unroll
        for (int j = 0; j < 4; ++j) {
            int idx = t + j * 256;
            int n = idx & 63, kh = idx >> 6;
            float v0 = Bp[(size_t)(kb * 32 + 2 * kh) * HID + n];
            float v1 = Bp[(size_t)(kb * 32 + 2 * kh + 1) * HID + n];
            Bs[n * 20 + kh] = packh2(v0, v1);
        }
        __syncthreads();
#pragma unroll
        for (int ks = 0; ks < 2; ++ks) {
            int kh0 = ks * 8;
            uint32_t a0 = As[(wrow + g) * 20 + kh0 + tg];
            uint32_t a1 = As[(wrow + g + 8) * 20 + kh0 + tg];
            uint32_t a2 = As[(wrow + g) * 20 + kh0 + tg + 4];
            uint32_t a3 = As[(wrow + g + 8) * 20 + kh0 + tg + 4];
#pragma unroll
            for (int nt = 0; nt < 8; ++nt) {
                int n = nt * 8 + g;
                uint32_t b0 = Bs[n * 20 + kh0 + tg];
                uint32_t b1 = Bs[n * 20 + kh0 + tg + 4];
                mma_f16(c[nt], a0, a1, a2, a3, b0, b1);
            }
        }
        __syncthreads();
    }

    int r0 = rowBase + wrow + g, r1 = r0 + 8;
#pragma unroll
    for (int nt = 0; nt < 8; ++nt) {
        int col = nt * 8 + tg * 2;
        if (r0 < M)
            *reinterpret_cast<__half2*>(Cp + (size_t)r0 * HID + col) = __floats2half2_rn(c[nt][0], c[nt][1]);
        if (r1 < M)
            *reinterpret_cast<__half2*>(Cp + (size_t)r1 * HID + col) = __floats2half2_rn(c[nt][2], c[nt][3]);
    }
}

// ---------------- fp16 HMMA output GEMM: fp16 A inputs, fp32 out ----------------
__global__ void gemm_out_f16(const __half* __restrict__ A0, const __half* __restrict__ A1,
                             const __half* __restrict__ A2, const __half* __restrict__ A3,
                             const float* __restrict__ B0, const float* __restrict__ B1,
                             const float* __restrict__ B2, const float* __restrict__ B3,
                             float* __restrict__ C, int M) {
    __shared__ uint32_t As[128 * 20];
    __shared__ uint32_t Bs[64 * 20];
    const int t = threadIdx.x;
    const int wid = t >> 5, lane = t & 31;
    const int g = lane >> 2, tg = lane & 3;
    const int rowBase = blockIdx.x * 128;
    const int colBase = blockIdx.y * 64;
    const int wrow = wid * 16;

    const __half* Aps[4] = {A0, A1, A2, A3};
    const float* Bps[4] = {B0, B1, B2, B3};

    float c[8][4] = {};

    for (int m = 0; m < 4; ++m) {
        const __half* __restrict__ Ap = Aps[m];
        const float* __restrict__ Bp = Bps[m];
        for (int kb = 0; kb < 2; ++kb) {
#pragma unroll
            for (int j = 0; j < 2; ++j) {
                int idx = t + j * 256;
                int r = idx >> 2, q = idx & 3;
                int gr = rowBase + r;
                if (gr >= M) gr = M - 1;
                uint4 hv = *(const uint4*)(Ap + (size_t)gr * HID + kb * 32 + q * 8);
                uint32_t* d = &As[r * 20 + q * 4];
                d[0] = hv.x; d[1] = hv.y; d[2] = hv.z; d[3] = hv.w;
            }
#pragma unroll
            for (int j = 0; j < 4; ++j) {
                int idx = t + j * 256;
                int n = idx & 63, kh = idx >> 6;
                int col = colBase + n;
                float v0 = 0.f, v1 = 0.f;
                if (col < OUTF) {
                    v0 = Bp[(size_t)(kb * 32 + 2 * kh) * OUTF + col];
                    v1 = Bp[(size_t)(kb * 32 + 2 * kh + 1) * OUTF + col];
                }
                Bs[n * 20 + kh] = packh2(v0, v1);
            }
            __syncthreads();
#pragma unroll
            for (int ks = 0; ks < 2; ++ks) {
                int kh0 = ks * 8;
                uint32_t a0 = As[(wrow + g) * 20 + kh0 + tg];
                uint32_t a1 = As[(wrow + g + 8) * 20 + kh0 + tg];
                uint32_t a2 = As[(wrow + g) * 20 + kh0 + tg + 4];
                uint32_t a3 = As[(wrow + g + 8) * 20 + kh0 + tg + 4];
#pragma unroll
                for (int nt = 0; nt < 8; ++nt) {
                    int n = nt * 8 + g;
                    uint32_t b0 = Bs[n * 20 + kh0 + tg];
                    uint32_t b1 = Bs[n * 20 + kh0 + tg + 4];
                    mma_f16(c[nt], a0, a1, a2, a3, b0, b1);
                }
            }
            __syncthreads();
        }
    }

    int r0 = rowBase + wrow + g, r1 = r0 + 8;
#pragma unroll
    for (int nt = 0; nt < 8; ++nt) {
        int col = colBase + nt * 8 + tg * 2;
        if (col < OUTF) {
            float bia = g_bsum2[col];
            if (r0 < M) C[(size_t)r0 * OUTF + col] = c[nt][0] + bia;
            if (r1 < M) C[(size_t)r1 * OUTF + col] = c[nt][2] + bia;
        }
        if (col + 1 < OUTF) {
            float bib = g_bsum2[col + 1];
            if (r0 < M) C[(size_t)r0 * OUTF + col + 1] = c[nt][1] + bib;
            if (r1 < M) C[(size_t)r1 * OUTF + col + 1] = c[nt][3] + bib;
        }
    }
}

// ---------------- host launcher ----------------
static inline void* sym(const void* s) {
    void* p = nullptr;
    cudaGetSymbolAddress(&p, s);
    return p;
}

extern "C" void kernel_launch(void* const* d_in, const int* in_sizes, int n_in,
                              void* d_out, int out_size) {
    static cudaStream_t s1 = nullptr, s2 = nullptr;
    static cudaEvent_t ev0 = nullptr, ev1 = nullptr, ev2 = nullptr, ev3 = nullptr, ev4 = nullptr;
    if (s1 == nullptr) {
        cudaStreamCreateWithFlags(&s1, cudaStreamNonBlocking);
        cudaStreamCreateWithFlags(&s2, cudaStreamNonBlocking);
        cudaEventCreateWithFlags(&ev0, cudaEventDisableTiming);
        cudaEventCreateWithFlags(&ev1, cudaEventDisableTiming);
        cudaEventCreateWithFlags(&ev2, cudaEventDisableTiming);
        cudaEventCreateWithFlags(&ev3, cudaEventDisableTiming);
        cudaEventCreateWithFlags(&ev4, cudaEventDisableTiming);
    }

    const float* x_paper  = (const float*)d_in[0];
    const float* x_author = (const float*)d_in[1];
    const float* x_field  = (const float*)d_in[2];
    const int* ei_wr = (const int*)d_in[3];
    const int* ei_rw = (const int*)d_in[4];
    const int* ei_ci = (const int*)d_in[5];
    const int* ei_ht = (const int*)d_in[6];
    const int* ei_rh = (const int*)d_in[7];
    const int nE_wr = in_sizes[3] / 2;
    const int nE_rw = in_sizes[4] / 2;
    const int nE_ci = in_sizes[5] / 2;
    const int nE_ht = in_sizes[6] / 2;
    const int nE_rh = in_sizes[7] / 2;

    const float* wl1_wr = (const float*)d_in[8];
    const float* wr1_wr = (const float*)d_in[9];
    const float* b1_wr  = (const float*)d_in[10];
    const float* wl1_rw = (const float*)d_in[11];
    const float* wr1_rw = (const float*)d_in[12];
    const float* b1_rw  = (const float*)d_in[13];
    const float* wl1_ci = (const float*)d_in[14];
    const float* wr1_ci = (const float*)d_in[15];
    const float* b1_ci  = (const float*)d_in[16];
    const float* wl1_ht = (const float*)d_in[17];
    const float* wr1_ht = (const float*)d_in[18];
    const float* b1_ht  = (const float*)d_in[19];
    const float* wl1_rh = (const float*)d_in[20];
    const float* wr1_rh = (const float*)d_in[21];
    const float* b1_rh  = (const float*)d_in[22];
    const float* wl2_wr = (const float*)d_in[23];
    const float* wr2_wr = (const float*)d_in[24];
    const float* b2_wr  = (const float*)d_in[25];
    const float* wl2_ci = (const float*)d_in[26];
    const float* wr2_ci = (const float*)d_in[27];
    const float* b2_ci  = (const float*)d_in[28];
    const float* wl2_rh = (const float*)d_in[29];
    const float* wr2_rh = (const float*)d_in[30];
    const float* b2_rh  = (const float*)d_in[31];

    float* out = (float*)d_out;

    __half* hs_wr = (__half*)sym(g_hs_wr);
    __half* hs_rw = (__half*)sym(g_hs_rw);
    __half* hs_ci = (__half*)sym(g_hs_ci);
    __half* hs_ht = (__half*)sym(g_hs_ht);
    __half* hs_rh = (__half*)sym(g_hs_rh);
    __half* selfP = (__half*)sym(g_selfP);
    __half* selfA = (__half*)sym(g_selfA);
    __half* selfF = (__half*)sym(g_selfF);
    __half* a1h = (__half*)sym(g_a1h);
    __half* f1h = (__half*)sym(g_f1h);
    __half* p1h = (__half*)sym(g_p1h);
    __half* m2_wr = (__half*)sym(g_m2_wr);
    __half* m2_ci = (__half*)sym(g_m2_ci);
    __half* m2_rh = (__half*)sym(g_m2_rh);
    int* cnt = (int*)sym(g_cnt);
    int* rp_wr = (int*)sym(g_rp_wr);
    int* rp_rw = (int*)sym(g_rp_rw);
    int* rp_ci = (int*)sym(g_rp_ci);
    int* rp_ht = (int*)sym(g_rp_ht);
    int* rp_rh = (int*)sym(g_rp_rh);
    int* csr_wr = (int*)sym(g_csr_wr);
    int* csr_rw = (int*)sym(g_csr_rw);
    int* csr_ci = (int*)sym(g_csr_ci);
    int* csr_ht = (int*)sym(g_csr_ht);
    int* csr_rh = (int*)sym(g_csr_rh);
    float* wsumP = (float*)sym(g_wsumP);
    float* w2sum = (float*)sym(g_w2sum);

    // ---- fork: s1 does weight prep + layer-1 GEMMs ----
    cudaEventRecord(ev0, 0);
    cudaStreamWaitEvent(s1, ev0, 0);

    prep_weights<<<(HID * OUTF + 255) / 256, 256, 0, s1>>>(
        wr1_wr, wr1_ci, wr1_rh, wr2_wr, wr2_ci, wr2_rh,
        b1_wr, b1_ci, b1_rh, b2_wr, b2_ci, b2_rh);

    const int gP = (NP + 127) / 128, gA = (NA + 127) / 128, gF = (NF + 127) / 128;
    {
        GemmBatch bp;
        bp.B[0] = wl1_rw; bp.C[0] = hs_rw;
        bp.B[1] = wl1_ci; bp.C[1] = hs_ci;
        bp.B[2] = wl1_ht; bp.C[2] = hs_ht;
        bp.B[3] = wsumP;  bp.C[3] = selfP;
        gemm_f16_f128<<<dim3(gP, 4), 256, 0, s1>>>(x_paper, bp, NP);
        GemmBatch ba;
        ba.B[0] = wl1_wr; ba.C[0] = hs_wr;
        ba.B[1] = wr1_rw; ba.C[1] = selfA;
        ba.B[2] = wl1_wr; ba.C[2] = hs_wr;
        ba.B[3] = wl1_wr; ba.C[3] = hs_wr;
        gemm_f16_f128<<<dim3(gA, 2), 256, 0, s1>>>(x_author, ba, NA);
        GemmBatch bf;
        bf.B[0] = wl1_rh; bf.C[0] = hs_rh;
        bf.B[1] = wr1_ht; bf.C[1] = selfF;
        bf.B[2] = wl1_rh; bf.C[2] = hs_rh;
        bf.B[3] = wl1_rh; bf.C[3] = hs_rh;
        gemm_f16_f128<<<dim3(gF, 2), 256, 0, s1>>>(x_field, bf, NF);
    }
    cudaEventRecord(ev1, s1);

    // ---- stream 0: CSR build ----
    cudaMemsetAsync(cnt, 0, sizeof(int) * CNT_TOT, 0);

    EJobs ep;
    ep.ei[0] = ei_wr; ep.E[0] = nE_wr;
    ep.ei[1] = ei_rw; ep.E[1] = nE_rw;
    ep.ei[2] = ei_ci; ep.E[2] = nE_ci;
    ep.ei[3] = ei_ht; ep.E[3] = nE_ht;
    ep.ei[4] = ei_rh; ep.E[4] = nE_rh;
    ep.bs[0] = 0;
    for (int i = 0; i < 5; ++i) ep.bs[i + 1] = ep.bs[i] + (ep.E[i] + 255) / 256;

    k_count_all<<<ep.bs[5], 256>>>(ep);
    k_blocksum_all<<<dim3((NP + 1023) / 1024, 5), 256>>>();
    k_scan_bsums_all<<<5, 256>>>();
    k_scan_write_all<<<dim3((NP + 1023) / 1024, 5), 256>>>();
    k_fill_all<<<ep.bs[5], 256>>>(ep);
    cudaEventRecord(ev2, 0);

    auto wg = [](int n) { return (n * 32 + 255) / 256; };

    // ---- stream 0 chain: paper layer-1 -> layer-2 ci pull ----
    cudaStreamWaitEvent(0, ev1, 0);      // needs hs_* from s1
    k_paper_warp<<<wg(NP), 256>>>();
    k_l2_warp<<<wg(NP), 256>>>(p1h, rp_ci, csr_ci, m2_ci, NP);

    // ---- s1 chain: author layer-1 -> layer-2 wr pull ----
    cudaStreamWaitEvent(s1, ev2, 0);     // needs CSR from stream 0
    k_af_warp<<<wg(NA), 256, 0, s1>>>(hs_rw, rp_rw, csr_rw, selfA, b1_rw, a1h, NA);
    k_l2_warp<<<wg(NP), 256, 0, s1>>>(a1h, rp_wr, csr_wr, m2_wr, NP);
    cudaEventRecord(ev3, s1);

    // ---- s2 chain: field layer-1 -> layer-2 rh pull ----
    cudaStreamWaitEvent(s2, ev1, 0);
    cudaStreamWaitEvent(s2, ev2, 0);
    k_af_warp<<<wg(NF), 256, 0, s2>>>(hs_ht, rp_ht, csr_ht, selfF, b1_ht, f1h, NF);
    k_l2_warp<<<wg(NP), 256, 0, s2>>>(f1h, rp_rh, csr_rh, m2_rh, NP);
    cudaEventRecord(ev4, s2);

    // ---- join + output GEMM ----
    cudaStreamWaitEvent(0, ev3, 0);
    cudaStreamWaitEvent(0, ev4, 0);
    dim3 g2(gP, (OUTF + 63) / 64);
    gemm_out_f16<<<g2, 256>>>(m2_wr, m2_ci, m2_rh, p1h,
                              wl2_wr, wl2_ci, wl2_rh, w2sum,
                              out, NP);
}